// round 8
// baseline (speedup 1.0000x reference)
#include <cuda_runtime.h>
#include <cuda_bf16.h>
#include <cstdint>

// Problem constants (fixed shapes per reference)
#define T_SEQ   4096
#define DMODEL  1024
#define NHEADS  16
#define DHEAD   64
#define CHUNK   64
#define NCHUNK  (T_SEQ / CHUNK)        // 64
#define QK_SCALE 0.125f                // 1/sqrt(64)
#define BATCH   2
#define MROWS   (BATCH * T_SEQ)        // 8192
#define FIX_TH  3e-3f
#define FIX_CAP (1 << 18)

// fp32 scratch
#define BHTD (BATCH * NHEADS * T_SEQ * DHEAD)
__device__ float g_Q[BHTD];
__device__ float g_K[BHTD];
__device__ float g_V[BHTD];
__device__ float g_CKV[BHTD];
__device__ float g_O[BHTD];

// bf16 split scratch (h = bf16(x), m = bf16(x - h))
__device__ __nv_bfloat16 g_Xh[MROWS * DMODEL];
__device__ __nv_bfloat16 g_Xm[MROWS * DMODEL];
__device__ __nv_bfloat16 g_Wqh[3 * DMODEL * DMODEL];
__device__ __nv_bfloat16 g_Wqm[3 * DMODEL * DMODEL];
__device__ __nv_bfloat16 g_Woh[DMODEL * DMODEL];
__device__ __nv_bfloat16 g_Wom[DMODEL * DMODEL];
__device__ __nv_bfloat16 g_Oh[BHTD];
__device__ __nv_bfloat16 g_Om[BHTD];

// near-zero K/V fixup list
__device__ int g_fix_cnt;
__device__ int g_fix_idx[FIX_CAP];

// ---------------------------------------------------------------------------
// helpers
// ---------------------------------------------------------------------------
__device__ __forceinline__ uint32_t smem_u32(const void* p) {
    uint32_t a;
    asm("{ .reg .u64 t; cvta.to.shared.u64 t, %1; cvt.u32.u64 %0, t; }" : "=r"(a) : "l"(p));
    return a;
}
__device__ __forceinline__ void cp16(uint32_t dst, const void* src) {
    asm volatile("cp.async.cg.shared.global [%0], [%1], 16;" :: "r"(dst), "l"(src));
}
__device__ __forceinline__ void cp_commit() {
    asm volatile("cp.async.commit_group;");
}
__device__ __forceinline__ void cp_wait2() {
    asm volatile("cp.async.wait_group 2;" ::: "memory");
}
__device__ __forceinline__ void ldmat4(uint32_t* r, uint32_t addr) {
    asm volatile("ldmatrix.sync.aligned.m8n8.x4.shared.b16 {%0,%1,%2,%3}, [%4];"
                 : "=r"(r[0]), "=r"(r[1]), "=r"(r[2]), "=r"(r[3]) : "r"(addr));
}
__device__ __forceinline__ void mma16816(float* c, const uint32_t* a, uint32_t b0, uint32_t b1) {
    asm volatile(
        "mma.sync.aligned.m16n8k16.row.col.f32.bf16.bf16.f32 "
        "{%0,%1,%2,%3}, {%4,%5,%6,%7}, {%8,%9}, {%0,%1,%2,%3};"
        : "+f"(c[0]), "+f"(c[1]), "+f"(c[2]), "+f"(c[3])
        : "r"(a[0]), "r"(a[1]), "r"(a[2]), "r"(a[3]), "r"(b0), "r"(b1));
}

// ---------------------------------------------------------------------------
// Split fp32 -> (h, m) bf16.  sel: 0=x, 1=w_qkv, 2=w_o, 3=g_O
// ---------------------------------------------------------------------------
__global__ __launch_bounds__(256) void split_kernel(const float* __restrict__ srcArg,
                                                    int n, int sel) {
    const float* src = srcArg;
    __nv_bfloat16 *hp, *mp;
    if (sel == 0)      { hp = g_Xh;  mp = g_Xm;  }
    else if (sel == 1) { hp = g_Wqh; mp = g_Wqm; }
    else if (sel == 2) { hp = g_Woh; mp = g_Wom; }
    else               { src = g_O;  hp = g_Oh;  mp = g_Om; }
    int i = (blockIdx.x * 256 + threadIdx.x) * 4;
    if (i >= n) return;
    float4 v = *(const float4*)(src + i);
    float xs[4] = {v.x, v.y, v.z, v.w};
    __align__(8) __nv_bfloat16 hb[4], mb[4];
#pragma unroll
    for (int j = 0; j < 4; j++) {
        __nv_bfloat16 h = __float2bfloat16_rn(xs[j]);
        float r = xs[j] - __bfloat162float(h);
        hb[j] = h; mb[j] = __float2bfloat16_rn(r);
    }
    *(uint2*)(hp + i) = *(uint2*)hb;
    *(uint2*)(mp + i) = *(uint2*)mb;
}

__global__ void reset_cnt_kernel() { if (threadIdx.x == 0) g_fix_cnt = 0; }

// ---------------------------------------------------------------------------
// Split-bf16 HMMA GEMM. CTA tile 128x128, 8 warps (warp tile 64x32), K-chunks
// of 32, 3-stage cp.async pipeline. Per chunk: 3 products (AhBh, AhBm, AmBh).
// MODE 0: QKV = X @ Wqkv^T -> scale/binarize/scatter (+near-zero flags)
// MODE 1: out = O(gathered) @ Wo^T -> plain store
// ---------------------------------------------------------------------------
#define LDP     40                           // padded row pitch (elements)
#define TILE_E  (128 * LDP)                  // elements per tile
#define TILE_B2 (TILE_E * 2)                 // bytes per tile
#define STAGE_B (4 * TILE_B2)                // Ah, Am, Bh, Bm (40960 B)
#define NSTAGE  3
#define GEMM_SMEM (NSTAGE * STAGE_B)         // 122880 bytes

template<int MODE>
__global__ __launch_bounds__(256) void gemm_mma(float* __restrict__ outp) {
    extern __shared__ __align__(128) char smc[];
    const uint32_t smb = smem_u32(smc);
    const int tid = threadIdx.x;
    const int wid = tid >> 5;
    const int lane = tid & 31;
    const int bn = blockIdx.x * 128;
    const int bm = blockIdx.y * 128;
    const int wm = wid & 1;      // 2 m-blocks of 64
    const int wn = wid >> 1;     // 4 n-blocks of 32

    // gmem source bases
    const __nv_bfloat16 *Ah, *Am, *Bh, *Bm;
    int bb = 0, tbase = 0;
    if (MODE == 0) {
        Ah = g_Xh + (size_t)bm * DMODEL;  Am = g_Xm + (size_t)bm * DMODEL;
        Bh = g_Wqh + (size_t)bn * DMODEL; Bm = g_Wqm + (size_t)bn * DMODEL;
    } else {
        bb = bm >> 12; tbase = bm & (T_SEQ - 1);
        Ah = g_Oh; Am = g_Om;
        Bh = g_Woh + (size_t)bn * DMODEL; Bm = g_Wom + (size_t)bn * DMODEL;
    }

    // per-thread gmem->smem slots: 2 cp16 per tile
    const int ldrow0 = tid >> 2;         // 0..63
    const int ldcq = tid & 3;            // 0..3 (8 bf16 each)

    auto load_stage = [&](int c, int st) {
        const int k0 = c * 32;
        const uint32_t stg = smb + (uint32_t)st * STAGE_B;
#pragma unroll
        for (int t = 0; t < 4; t++) {
            const __nv_bfloat16* base;
            size_t roff; int rstride;
            if (MODE == 0 || t >= 2) {
                base = (t == 0) ? Ah : (t == 1) ? Am : (t == 2) ? Bh : Bm;
                roff = (size_t)k0 + ldcq * 8; rstride = DMODEL;
            } else {
                base = (t == 0) ? Ah : Am;
                int bh = bb * NHEADS + (k0 >> 6);
                roff = ((size_t)bh * T_SEQ + tbase) * DHEAD + (k0 & 63) + ldcq * 8;
                rstride = DHEAD;
            }
            const uint32_t tb = stg + (uint32_t)t * TILE_B2;
#pragma unroll
            for (int i = 0; i < 2; i++) {
                int row = ldrow0 + i * 64;
                cp16(tb + (uint32_t)(row * LDP + ldcq * 8) * 2,
                     base + roff + (size_t)row * rstride);
            }
        }
        cp_commit();
    };

    // ldmatrix lane address bases (relative element offsets within a tile)
    const int a_base = (wm * 64 + (lane & 15)) * LDP + (lane >> 4) * 8;
    const int b_base = (wn * 32 + (lane & 7) + (lane >> 4) * 8) * LDP + ((lane >> 3) & 1) * 8;

    float acc[4][4][4];
#pragma unroll
    for (int i = 0; i < 4; i++)
#pragma unroll
        for (int j = 0; j < 4; j++)
#pragma unroll
            for (int r = 0; r < 4; r++) acc[i][j][r] = 0.f;

    const int prodA[3] = {0, 0, 1};   // Ah, Ah, Am
    const int prodB[3] = {2, 3, 2};   // Bh, Bm, Bh

    const int NCH = DMODEL / 32;      // 32
    load_stage(0, 0);
    load_stage(1, 1);
    for (int c = 0; c < NCH; c++) {
        if (c + 2 < NCH) load_stage(c + 2, (c + 2) % NSTAGE);
        else cp_commit();             // empty group keeps the count advancing
        cp_wait2();
        __syncthreads();
        const uint32_t stg = smb + (uint32_t)(c % NSTAGE) * STAGE_B;
#pragma unroll
        for (int p = 0; p < 3; p++) {
            const uint32_t At = stg + (uint32_t)prodA[p] * TILE_B2;
            const uint32_t Bt = stg + (uint32_t)prodB[p] * TILE_B2;
#pragma unroll
            for (int s = 0; s < 2; s++) {
                uint32_t a[4][4], b[2][4];
#pragma unroll
                for (int mi = 0; mi < 4; mi++)
                    ldmat4(a[mi], At + (uint32_t)(a_base + mi * 16 * LDP + s * 16) * 2);
#pragma unroll
                for (int ni2 = 0; ni2 < 2; ni2++)
                    ldmat4(b[ni2], Bt + (uint32_t)(b_base + ni2 * 16 * LDP + s * 16) * 2);
#pragma unroll
                for (int mi = 0; mi < 4; mi++)
#pragma unroll
                    for (int ni = 0; ni < 4; ni++)
                        mma16816(acc[mi][ni], a[mi], b[ni >> 1][(ni & 1) * 2],
                                 b[ni >> 1][(ni & 1) * 2 + 1]);
            }
        }
        __syncthreads();
    }

    // epilogue: D frag (m16n8): c0,c1 row=lane>>2, cols 2*(lane&3)+{0,1}; c2,c3 row+8
    const int r0l = lane >> 2;
    const int cbl = (lane & 3) * 2;
#pragma unroll
    for (int mi = 0; mi < 4; mi++) {
#pragma unroll
        for (int ni = 0; ni < 4; ni++) {
#pragma unroll
            for (int half = 0; half < 2; half++) {
                int row = bm + wm * 64 + mi * 16 + r0l + half * 8;
                int col = bn + wn * 32 + ni * 8 + cbl;
                float v0 = acc[mi][ni][half * 2];
                float v1 = acc[mi][ni][half * 2 + 1];
                if (MODE == 0) {
                    int mb = row >> 12, t = row & (T_SEQ - 1);
                    int which = col >> 10, h = (col >> 6) & 15, l = col & 63;
                    size_t dst = (((size_t)(mb * NHEADS + h)) * T_SEQ + t) * DHEAD + l;
                    if (which == 0) {
                        float2 o; o.x = v0 * QK_SCALE; o.y = v1 * QK_SCALE;
                        *(float2*)(g_Q + dst) = o;
                    } else {
                        float* base = (which == 1) ? g_K : g_V;
                        float2 o;
                        o.x = (v0 >= 0.f) ? 1.f : -1.f;
                        o.y = (v1 >= 0.f) ? 1.f : -1.f;
                        *(float2*)(base + dst) = o;
                        if (fabsf(v0) < FIX_TH) {
                            int idx = atomicAdd(&g_fix_cnt, 1);
                            if (idx < FIX_CAP) g_fix_idx[idx] = row * 3072 + col;
                        }
                        if (fabsf(v1) < FIX_TH) {
                            int idx = atomicAdd(&g_fix_cnt, 1);
                            if (idx < FIX_CAP) g_fix_idx[idx] = row * 3072 + col + 1;
                        }
                    }
                } else {
                    float2 o; o.x = v0; o.y = v1;
                    *(float2*)(outp + (size_t)row * DMODEL + col) = o;
                }
            }
        }
    }
}

// ---------------------------------------------------------------------------
// Exact fp32 recompute of flagged near-zero K/V elements. One thread per
// element, STRICTLY SEQUENTIAL k-order FMA chain (matches the summation order
// that empirically reproduced the reference's signs in rounds 1 and 6).
// ---------------------------------------------------------------------------
__global__ __launch_bounds__(256) void fixup_kernel(const float* __restrict__ x,
                                                    const float* __restrict__ w) {
    int cnt = g_fix_cnt; if (cnt > FIX_CAP) cnt = FIX_CAP;
    const int stride = gridDim.x * blockDim.x;
    for (int i = blockIdx.x * blockDim.x + threadIdx.x; i < cnt; i += stride) {
        int code = g_fix_idx[i];
        int m = code / 3072, n = code % 3072;
        const float4* xr = (const float4*)(x + (size_t)m * DMODEL);
        const float4* wr = (const float4*)(w + (size_t)n * DMODEL);
        float acc = 0.f;
#pragma unroll 4
        for (int j = 0; j < DMODEL / 4; j++) {
            float4 a = xr[j], b = wr[j];
            acc = fmaf(a.x, b.x, acc);
            acc = fmaf(a.y, b.y, acc);
            acc = fmaf(a.z, b.z, acc);
            acc = fmaf(a.w, b.w, acc);
        }
        int mb = m >> 12, t = m & (T_SEQ - 1);
        int h = (n >> 6) & 15, l = n & 63;
        float* base = ((n >> 10) == 1) ? g_K : g_V;
        base[(((size_t)(mb * NHEADS + h)) * T_SEQ + t) * DHEAD + l] = (acc >= 0.f) ? 1.f : -1.f;
    }
}

// ---------------------------------------------------------------------------
// chunk_kv[bh][n][k][v] = sum_t kc[t][k] * vc[t][v]
// ---------------------------------------------------------------------------
__global__ __launch_bounds__(256) void chunk_kv_kernel() {
    __shared__ float ks[CHUNK * DHEAD];
    __shared__ float vs[CHUNK * DHEAD];
    const int tid = threadIdx.x;
    const int n = blockIdx.x & (NCHUNK - 1);
    const int bh = blockIdx.x >> 6;
    const float* kg = g_K + ((size_t)bh * T_SEQ + n * CHUNK) * DHEAD;
    const float* vg = g_V + ((size_t)bh * T_SEQ + n * CHUNK) * DHEAD;
    for (int f = tid; f < 1024; f += 256) {
        ((float4*)ks)[f] = ((const float4*)kg)[f];
        ((float4*)vs)[f] = ((const float4*)vg)[f];
    }
    __syncthreads();
    const int kk0 = (tid >> 4) * 4;
    const int vv0 = (tid & 15) * 4;
    float acc[4][4] = {};
#pragma unroll 4
    for (int t = 0; t < CHUNK; t++) {
        float kv[4];
        *(float4*)kv = *(const float4*)&ks[t * DHEAD + kk0];
        float4 v4 = *(const float4*)&vs[t * DHEAD + vv0];
#pragma unroll
        for (int ii = 0; ii < 4; ii++) {
            acc[ii][0] += kv[ii] * v4.x;
            acc[ii][1] += kv[ii] * v4.y;
            acc[ii][2] += kv[ii] * v4.z;
            acc[ii][3] += kv[ii] * v4.w;
        }
    }
    float* cg = g_CKV + ((size_t)bh * NCHUNK + n) * (DHEAD * DHEAD);
#pragma unroll
    for (int ii = 0; ii < 4; ii++) {
        float4 o; o.x = acc[ii][0]; o.y = acc[ii][1]; o.z = acc[ii][2]; o.w = acc[ii][3];
        *(float4*)&cg[(kk0 + ii) * DHEAD + vv0] = o;
    }
}

// ---------------------------------------------------------------------------
// In-place exclusive prefix over chunks; writes final_state.
// Software prefetch: chunk n+1's loads issue before chunk n's store+accumulate,
// converting the 64-long latency chain into overlapped traffic.
// ---------------------------------------------------------------------------
__global__ __launch_bounds__(256) void prefix_kernel(float* __restrict__ final_out) {
    const int tid = threadIdx.x;
    const int bh = blockIdx.x;
    float* base = g_CKV + (size_t)bh * NCHUNK * (DHEAD * DHEAD) + tid * 16;
    float run[16], cur[16], nxt[16];
#pragma unroll
    for (int j = 0; j < 16; j++) run[j] = 0.f;
#pragma unroll
    for (int q = 0; q < 4; q++) ((float4*)cur)[q] = ((float4*)base)[q];
    for (int n = 0; n < NCHUNK; n++) {
        float* p = base + (size_t)n * (DHEAD * DHEAD);
        if (n + 1 < NCHUNK) {
            const float* pn = p + DHEAD * DHEAD;
#pragma unroll
            for (int q = 0; q < 4; q++) ((float4*)nxt)[q] = ((const float4*)pn)[q];
        }
#pragma unroll
        for (int q = 0; q < 4; q++) ((float4*)p)[q] = ((float4*)run)[q];
#pragma unroll
        for (int j = 0; j < 16; j++) run[j] += cur[j];
#pragma unroll
        for (int j = 0; j < 16; j++) cur[j] = nxt[j];
    }
    float* fo = final_out + (size_t)bh * (DHEAD * DHEAD) + tid * 16;
#pragma unroll
    for (int q = 0; q < 4; q++) ((float4*)fo)[q] = ((float4*)run)[q];
}

// ---------------------------------------------------------------------------
// Per-chunk attention: out = tril(q@k^T)@v + q@prefix
// ---------------------------------------------------------------------------
#define KT_PITCH 68
#define ATTN_SMEM_FLOATS (4096 + CHUNK * KT_PITCH + 4096 + 4096)

__global__ __launch_bounds__(256) void attn_chunk_kernel() {
    extern __shared__ float smf[];
    float* qs = smf;
    float* kp = smf + 4096;
    float* vs = kp + CHUNK * KT_PITCH;
    float* ss = vs + 4096;

    const int tid = threadIdx.x;
    const int n = blockIdx.x & (NCHUNK - 1);
    const int bh = blockIdx.x >> 6;

    const float* qg = g_Q + ((size_t)bh * T_SEQ + n * CHUNK) * DHEAD;
    const float* kg = g_K + ((size_t)bh * T_SEQ + n * CHUNK) * DHEAD;
    const float* vg = g_V + ((size_t)bh * T_SEQ + n * CHUNK) * DHEAD;

    for (int f = tid; f < 1024; f += 256) {
        ((float4*)qs)[f] = ((const float4*)qg)[f];
        ((float4*)vs)[f] = ((const float4*)vg)[f];
        int j = f >> 4;
        int lq = (f & 15) << 2;
        float4 kv = ((const float4*)kg)[f];
        kp[(lq + 0) * KT_PITCH + j] = kv.x;
        kp[(lq + 1) * KT_PITCH + j] = kv.y;
        kp[(lq + 2) * KT_PITCH + j] = kv.z;
        kp[(lq + 3) * KT_PITCH + j] = kv.w;
    }
    __syncthreads();

    const int i0 = (tid >> 4) * 4;
    const int c0 = (tid & 15) * 4;

    {
        float sa[4][4] = {};
#pragma unroll 4
        for (int l = 0; l < DHEAD; l++) {
            float q4[4];
#pragma unroll
            for (int ii = 0; ii < 4; ii++) q4[ii] = qs[(i0 + ii) * DHEAD + l];
            float4 k4 = *(const float4*)&kp[l * KT_PITCH + c0];
#pragma unroll
            for (int ii = 0; ii < 4; ii++) {
                sa[ii][0] += q4[ii] * k4.x;
                sa[ii][1] += q4[ii] * k4.y;
                sa[ii][2] += q4[ii] * k4.z;
                sa[ii][3] += q4[ii] * k4.w;
            }
        }
#pragma unroll
        for (int ii = 0; ii < 4; ii++) {
            int i = i0 + ii;
#pragma unroll
            for (int jj = 0; jj < 4; jj++) {
                int j = c0 + jj;
                ss[i * CHUNK + j] = (j <= i) ? sa[ii][jj] : 0.f;
            }
        }
    }
    __syncthreads();

    {
        const float* pg = g_CKV + ((size_t)bh * NCHUNK + n) * (DHEAD * DHEAD);
        for (int f = tid; f < 1024; f += 256) ((float4*)kp)[f] = ((const float4*)pg)[f];
    }
    __syncthreads();

    {
        float oa[4][4] = {};
#pragma unroll 4
        for (int j = 0; j < CHUNK; j++) {
            float s4[4];
#pragma unroll
            for (int ii = 0; ii < 4; ii++) s4[ii] = ss[(i0 + ii) * CHUNK + j];
            float4 v4 = *(const float4*)&vs[j * DHEAD + c0];
#pragma unroll
            for (int ii = 0; ii < 4; ii++) {
                oa[ii][0] += s4[ii] * v4.x;
                oa[ii][1] += s4[ii] * v4.y;
                oa[ii][2] += s4[ii] * v4.z;
                oa[ii][3] += s4[ii] * v4.w;
            }
        }
#pragma unroll 4
        for (int k = 0; k < DHEAD; k++) {
            float q4[4];
#pragma unroll
            for (int ii = 0; ii < 4; ii++) q4[ii] = qs[(i0 + ii) * DHEAD + k];
            float4 p4 = *(const float4*)&kp[k * DHEAD + c0];
#pragma unroll
            for (int ii = 0; ii < 4; ii++) {
                oa[ii][0] += q4[ii] * p4.x;
                oa[ii][1] += q4[ii] * p4.y;
                oa[ii][2] += q4[ii] * p4.z;
                oa[ii][3] += q4[ii] * p4.w;
            }
        }
        float* og = g_O + ((size_t)bh * T_SEQ + n * CHUNK) * DHEAD;
#pragma unroll
        for (int ii = 0; ii < 4; ii++) {
            float4 o; o.x = oa[ii][0]; o.y = oa[ii][1]; o.z = oa[ii][2]; o.w = oa[ii][3];
            *(float4*)&og[(i0 + ii) * DHEAD + c0] = o;
        }
    }
}

// ---------------------------------------------------------------------------
extern "C" void kernel_launch(void* const* d_in, const int* in_sizes, int n_in,
                              void* d_out, int out_size) {
    const float* x     = (const float*)d_in[0];
    const float* w_qkv = (const float*)d_in[1];
    const float* w_o   = (const float*)d_in[2];
    float* out = (float*)d_out;

    const int M = in_sizes[0] / DMODEL;    // 8192
    const int BH = (M / T_SEQ) * NHEADS;   // 32

    cudaFuncSetAttribute(gemm_mma<0>, cudaFuncAttributeMaxDynamicSharedMemorySize, GEMM_SMEM);
    cudaFuncSetAttribute(gemm_mma<1>, cudaFuncAttributeMaxDynamicSharedMemorySize, GEMM_SMEM);
    cudaFuncSetAttribute(attn_chunk_kernel, cudaFuncAttributeMaxDynamicSharedMemorySize,
                         ATTN_SMEM_FLOATS * (int)sizeof(float));

    reset_cnt_kernel<<<1, 32>>>();
    split_kernel<<<(M * DMODEL) / 1024, 256>>>(x, M * DMODEL, 0);
    split_kernel<<<(3 * DMODEL * DMODEL) / 1024, 256>>>(w_qkv, 3 * DMODEL * DMODEL, 1);
    split_kernel<<<(DMODEL * DMODEL) / 1024, 256>>>(w_o, DMODEL * DMODEL, 2);

    dim3 g1(3 * DMODEL / 128, M / 128);
    gemm_mma<0><<<g1, 256, GEMM_SMEM>>>(nullptr);

    fixup_kernel<<<256, 256>>>(x, w_qkv);

    chunk_kv_kernel<<<BH * NCHUNK, 256>>>();
    prefix_kernel<<<BH, 256>>>(out + (size_t)M * DMODEL);
    attn_chunk_kernel<<<BH * NCHUNK, 256, ATTN_SMEM_FLOATS * (int)sizeof(float)>>>();

    split_kernel<<<(M * DMODEL) / 1024, 256>>>(nullptr, M * DMODEL, 3);
    dim3 g2(DMODEL / 128, M / 128);
    gemm_mma<1><<<g2, 256, GEMM_SMEM>>>(out);
}

// round 9
// speedup vs baseline: 1.1047x; 1.1047x over previous
#include <cuda_runtime.h>
#include <cuda_bf16.h>
#include <cstdint>

// Problem constants (fixed shapes per reference)
#define T_SEQ   4096
#define DMODEL  1024
#define NHEADS  16
#define DHEAD   64
#define CHUNK   64
#define NCHUNK  (T_SEQ / CHUNK)        // 64
#define QK_SCALE 0.125f                // 1/sqrt(64)
#define BATCH   2
#define MROWS   (BATCH * T_SEQ)        // 8192
#define FIX_TH  3e-3f
#define FIX_CAP (1 << 18)

// fp32 scratch
#define BHTD (BATCH * NHEADS * T_SEQ * DHEAD)
__device__ float g_Q[BHTD];
__device__ float g_K[BHTD];
__device__ float g_V[BHTD];
__device__ float g_CKV[BHTD];
__device__ float g_O[BHTD];

// bf16 split scratch (h = bf16(x), m = bf16(x - h))
__device__ __nv_bfloat16 g_Xh[MROWS * DMODEL];
__device__ __nv_bfloat16 g_Xm[MROWS * DMODEL];
__device__ __nv_bfloat16 g_Wqh[3 * DMODEL * DMODEL];
__device__ __nv_bfloat16 g_Wqm[3 * DMODEL * DMODEL];
__device__ __nv_bfloat16 g_Woh[DMODEL * DMODEL];
__device__ __nv_bfloat16 g_Wom[DMODEL * DMODEL];
__device__ __nv_bfloat16 g_Oh[BHTD];
__device__ __nv_bfloat16 g_Om[BHTD];

// near-zero K/V fixup list
__device__ int g_fix_cnt;
__device__ int g_fix_idx[FIX_CAP];

// ---------------------------------------------------------------------------
// helpers
// ---------------------------------------------------------------------------
__device__ __forceinline__ uint32_t smem_u32(const void* p) {
    uint32_t a;
    asm("{ .reg .u64 t; cvta.to.shared.u64 t, %1; cvt.u32.u64 %0, t; }" : "=r"(a) : "l"(p));
    return a;
}
__device__ __forceinline__ void cp16(uint32_t dst, const void* src) {
    asm volatile("cp.async.cg.shared.global [%0], [%1], 16;" :: "r"(dst), "l"(src));
}
__device__ __forceinline__ void cp_commit() {
    asm volatile("cp.async.commit_group;");
}
__device__ __forceinline__ void cp_wait1() {
    asm volatile("cp.async.wait_group 1;" ::: "memory");
}
__device__ __forceinline__ void cp_wait0() {
    asm volatile("cp.async.wait_group 0;" ::: "memory");
}
__device__ __forceinline__ void ldmat4(uint32_t* r, uint32_t addr) {
    asm volatile("ldmatrix.sync.aligned.m8n8.x4.shared.b16 {%0,%1,%2,%3}, [%4];"
                 : "=r"(r[0]), "=r"(r[1]), "=r"(r[2]), "=r"(r[3]) : "r"(addr));
}
__device__ __forceinline__ void mma16816(float* c, const uint32_t* a, uint32_t b0, uint32_t b1) {
    asm volatile(
        "mma.sync.aligned.m16n8k16.row.col.f32.bf16.bf16.f32 "
        "{%0,%1,%2,%3}, {%4,%5,%6,%7}, {%8,%9}, {%0,%1,%2,%3};"
        : "+f"(c[0]), "+f"(c[1]), "+f"(c[2]), "+f"(c[3])
        : "r"(a[0]), "r"(a[1]), "r"(a[2]), "r"(a[3]), "r"(b0), "r"(b1));
}

// ---------------------------------------------------------------------------
// Split fp32 -> (h, m) bf16.  sel: 0=x, 1=w_qkv, 2=w_o, 3=g_O
// ---------------------------------------------------------------------------
__global__ __launch_bounds__(256) void split_kernel(const float* __restrict__ srcArg,
                                                    int n, int sel) {
    const float* src = srcArg;
    __nv_bfloat16 *hp, *mp;
    if (sel == 0)      { hp = g_Xh;  mp = g_Xm;  }
    else if (sel == 1) { hp = g_Wqh; mp = g_Wqm; }
    else if (sel == 2) { hp = g_Woh; mp = g_Wom; }
    else               { src = g_O;  hp = g_Oh;  mp = g_Om; }
    int i = (blockIdx.x * 256 + threadIdx.x) * 4;
    if (i >= n) return;
    float4 v = *(const float4*)(src + i);
    float xs[4] = {v.x, v.y, v.z, v.w};
    __align__(8) __nv_bfloat16 hb[4], mb[4];
#pragma unroll
    for (int j = 0; j < 4; j++) {
        __nv_bfloat16 h = __float2bfloat16_rn(xs[j]);
        float r = xs[j] - __bfloat162float(h);
        hb[j] = h; mb[j] = __float2bfloat16_rn(r);
    }
    *(uint2*)(hp + i) = *(uint2*)hb;
    *(uint2*)(mp + i) = *(uint2*)mb;
}

__global__ void reset_cnt_kernel() { if (threadIdx.x == 0) g_fix_cnt = 0; }

// ---------------------------------------------------------------------------
// Split-bf16 HMMA GEMM. CTA tile 128x128, 8 warps (warp tile 64x32), K-chunks
// of 32, double-buffered cp.async (the proven R5 configuration). Per chunk:
// 3 products (AhBh, AhBm, AmBh).
// MODE 0: QKV = X @ Wqkv^T -> scale/binarize/scatter (+near-zero flags)
// MODE 1: out = O(gathered) @ Wo^T -> plain store
// ---------------------------------------------------------------------------
#define LDP     40                           // padded row pitch (elements)
#define TILE_E  (128 * LDP)                  // elements per tile
#define TILE_B2 (TILE_E * 2)                 // bytes per tile
#define STAGE_B (4 * TILE_B2)                // Ah, Am, Bh, Bm
#define GEMM_SMEM (2 * STAGE_B)              // 81920 bytes

template<int MODE>
__global__ __launch_bounds__(256) void gemm_mma(float* __restrict__ outp) {
    extern __shared__ __align__(128) char smc[];
    const uint32_t smb = smem_u32(smc);
    const int tid = threadIdx.x;
    const int wid = tid >> 5;
    const int lane = tid & 31;
    const int bn = blockIdx.x * 128;
    const int bm = blockIdx.y * 128;
    const int wm = wid & 1;      // 2 m-blocks of 64
    const int wn = wid >> 1;     // 4 n-blocks of 32

    // gmem source bases
    const __nv_bfloat16 *Ah, *Am, *Bh, *Bm;
    int bb = 0, tbase = 0;
    if (MODE == 0) {
        Ah = g_Xh + (size_t)bm * DMODEL;  Am = g_Xm + (size_t)bm * DMODEL;
        Bh = g_Wqh + (size_t)bn * DMODEL; Bm = g_Wqm + (size_t)bn * DMODEL;
    } else {
        bb = bm >> 12; tbase = bm & (T_SEQ - 1);
        Ah = g_Oh; Am = g_Om;
        Bh = g_Woh + (size_t)bn * DMODEL; Bm = g_Wom + (size_t)bn * DMODEL;
    }

    // per-thread gmem->smem slots: 2 cp16 per tile
    const int ldrow0 = tid >> 2;         // 0..63
    const int ldcq = tid & 3;            // 0..3 (8 bf16 each)

    auto load_stage = [&](int c, int st) {
        const int k0 = c * 32;
        const uint32_t stg = smb + (uint32_t)st * STAGE_B;
#pragma unroll
        for (int t = 0; t < 4; t++) {
            const __nv_bfloat16* base;
            size_t roff; int rstride;
            if (MODE == 0 || t >= 2) {
                base = (t == 0) ? Ah : (t == 1) ? Am : (t == 2) ? Bh : Bm;
                roff = (size_t)k0 + ldcq * 8; rstride = DMODEL;
            } else {
                base = (t == 0) ? Ah : Am;
                int bh = bb * NHEADS + (k0 >> 6);
                roff = ((size_t)bh * T_SEQ + tbase) * DHEAD + (k0 & 63) + ldcq * 8;
                rstride = DHEAD;
            }
            const uint32_t tb = stg + (uint32_t)t * TILE_B2;
#pragma unroll
            for (int i = 0; i < 2; i++) {
                int row = ldrow0 + i * 64;
                cp16(tb + (uint32_t)(row * LDP + ldcq * 8) * 2,
                     base + roff + (size_t)row * rstride);
            }
        }
        cp_commit();
    };

    // ldmatrix lane address bases (relative element offsets within a tile)
    const int a_base = (wm * 64 + (lane & 15)) * LDP + (lane >> 4) * 8;
    const int b_base = (wn * 32 + (lane & 7) + (lane >> 4) * 8) * LDP + ((lane >> 3) & 1) * 8;

    float acc[4][4][4];
#pragma unroll
    for (int i = 0; i < 4; i++)
#pragma unroll
        for (int j = 0; j < 4; j++)
#pragma unroll
            for (int r = 0; r < 4; r++) acc[i][j][r] = 0.f;

    const int prodA[3] = {0, 0, 1};   // Ah, Ah, Am
    const int prodB[3] = {2, 3, 2};   // Bh, Bm, Bh

    load_stage(0, 0);
    const int NCH = DMODEL / 32;      // 32
    for (int c = 0; c < NCH; c++) {
        if (c + 1 < NCH) { load_stage(c + 1, (c + 1) & 1); cp_wait1(); }
        else cp_wait0();
        __syncthreads();
        const uint32_t stg = smb + (uint32_t)(c & 1) * STAGE_B;
#pragma unroll
        for (int p = 0; p < 3; p++) {
            const uint32_t At = stg + (uint32_t)prodA[p] * TILE_B2;
            const uint32_t Bt = stg + (uint32_t)prodB[p] * TILE_B2;
#pragma unroll
            for (int s = 0; s < 2; s++) {
                uint32_t a[4][4], b[2][4];
#pragma unroll
                for (int mi = 0; mi < 4; mi++)
                    ldmat4(a[mi], At + (uint32_t)(a_base + mi * 16 * LDP + s * 16) * 2);
#pragma unroll
                for (int ni2 = 0; ni2 < 2; ni2++)
                    ldmat4(b[ni2], Bt + (uint32_t)(b_base + ni2 * 16 * LDP + s * 16) * 2);
#pragma unroll
                for (int mi = 0; mi < 4; mi++)
#pragma unroll
                    for (int ni = 0; ni < 4; ni++)
                        mma16816(acc[mi][ni], a[mi], b[ni >> 1][(ni & 1) * 2],
                                 b[ni >> 1][(ni & 1) * 2 + 1]);
            }
        }
        __syncthreads();
    }

    // epilogue: D frag (m16n8): c0,c1 row=lane>>2, cols 2*(lane&3)+{0,1}; c2,c3 row+8
    const int r0l = lane >> 2;
    const int cbl = (lane & 3) * 2;
#pragma unroll
    for (int mi = 0; mi < 4; mi++) {
#pragma unroll
        for (int ni = 0; ni < 4; ni++) {
#pragma unroll
            for (int half = 0; half < 2; half++) {
                int row = bm + wm * 64 + mi * 16 + r0l + half * 8;
                int col = bn + wn * 32 + ni * 8 + cbl;
                float v0 = acc[mi][ni][half * 2];
                float v1 = acc[mi][ni][half * 2 + 1];
                if (MODE == 0) {
                    int mb = row >> 12, t = row & (T_SEQ - 1);
                    int which = col >> 10, h = (col >> 6) & 15, l = col & 63;
                    size_t dst = (((size_t)(mb * NHEADS + h)) * T_SEQ + t) * DHEAD + l;
                    if (which == 0) {
                        float2 o; o.x = v0 * QK_SCALE; o.y = v1 * QK_SCALE;
                        *(float2*)(g_Q + dst) = o;
                    } else {
                        float* base = (which == 1) ? g_K : g_V;
                        float2 o;
                        o.x = (v0 >= 0.f) ? 1.f : -1.f;
                        o.y = (v1 >= 0.f) ? 1.f : -1.f;
                        *(float2*)(base + dst) = o;
                        if (fabsf(v0) < FIX_TH) {
                            int idx = atomicAdd(&g_fix_cnt, 1);
                            if (idx < FIX_CAP) g_fix_idx[idx] = row * 3072 + col;
                        }
                        if (fabsf(v1) < FIX_TH) {
                            int idx = atomicAdd(&g_fix_cnt, 1);
                            if (idx < FIX_CAP) g_fix_idx[idx] = row * 3072 + col + 1;
                        }
                    }
                } else {
                    float2 o; o.x = v0; o.y = v1;
                    *(float2*)(outp + (size_t)row * DMODEL + col) = o;
                }
            }
        }
    }
}

// ---------------------------------------------------------------------------
// Exact fp32 recompute of flagged near-zero K/V elements. One thread per
// element, STRICTLY SEQUENTIAL k-order FMA chain (matches the summation order
// that empirically reproduced the reference's signs in rounds 1 and 6-8).
// ---------------------------------------------------------------------------
__global__ __launch_bounds__(256) void fixup_kernel(const float* __restrict__ x,
                                                    const float* __restrict__ w) {
    int cnt = g_fix_cnt; if (cnt > FIX_CAP) cnt = FIX_CAP;
    const int stride = gridDim.x * blockDim.x;
    for (int i = blockIdx.x * blockDim.x + threadIdx.x; i < cnt; i += stride) {
        int code = g_fix_idx[i];
        int m = code / 3072, n = code % 3072;
        const float4* xr = (const float4*)(x + (size_t)m * DMODEL);
        const float4* wr = (const float4*)(w + (size_t)n * DMODEL);
        float acc = 0.f;
#pragma unroll 4
        for (int j = 0; j < DMODEL / 4; j++) {
            float4 a = xr[j], b = wr[j];
            acc = fmaf(a.x, b.x, acc);
            acc = fmaf(a.y, b.y, acc);
            acc = fmaf(a.z, b.z, acc);
            acc = fmaf(a.w, b.w, acc);
        }
        int mb = m >> 12, t = m & (T_SEQ - 1);
        int h = (n >> 6) & 15, l = n & 63;
        float* base = ((n >> 10) == 1) ? g_K : g_V;
        base[(((size_t)(mb * NHEADS + h)) * T_SEQ + t) * DHEAD + l] = (acc >= 0.f) ? 1.f : -1.f;
    }
}

// ---------------------------------------------------------------------------
// chunk_kv[bh][n][k][v] = sum_t kc[t][k] * vc[t][v]
// ---------------------------------------------------------------------------
__global__ __launch_bounds__(256) void chunk_kv_kernel() {
    __shared__ float ks[CHUNK * DHEAD];
    __shared__ float vs[CHUNK * DHEAD];
    const int tid = threadIdx.x;
    const int n = blockIdx.x & (NCHUNK - 1);
    const int bh = blockIdx.x >> 6;
    const float* kg = g_K + ((size_t)bh * T_SEQ + n * CHUNK) * DHEAD;
    const float* vg = g_V + ((size_t)bh * T_SEQ + n * CHUNK) * DHEAD;
    for (int f = tid; f < 1024; f += 256) {
        ((float4*)ks)[f] = ((const float4*)kg)[f];
        ((float4*)vs)[f] = ((const float4*)vg)[f];
    }
    __syncthreads();
    const int kk0 = (tid >> 4) * 4;
    const int vv0 = (tid & 15) * 4;
    float acc[4][4] = {};
#pragma unroll 4
    for (int t = 0; t < CHUNK; t++) {
        float kv[4];
        *(float4*)kv = *(const float4*)&ks[t * DHEAD + kk0];
        float4 v4 = *(const float4*)&vs[t * DHEAD + vv0];
#pragma unroll
        for (int ii = 0; ii < 4; ii++) {
            acc[ii][0] += kv[ii] * v4.x;
            acc[ii][1] += kv[ii] * v4.y;
            acc[ii][2] += kv[ii] * v4.z;
            acc[ii][3] += kv[ii] * v4.w;
        }
    }
    float* cg = g_CKV + ((size_t)bh * NCHUNK + n) * (DHEAD * DHEAD);
#pragma unroll
    for (int ii = 0; ii < 4; ii++) {
        float4 o; o.x = acc[ii][0]; o.y = acc[ii][1]; o.z = acc[ii][2]; o.w = acc[ii][3];
        *(float4*)&cg[(kk0 + ii) * DHEAD + vv0] = o;
    }
}

// ---------------------------------------------------------------------------
// In-place exclusive prefix over chunks; writes final_state.
// Software prefetch: chunk n+1's loads issue before chunk n's store+accumulate,
// converting the 64-long latency chain into overlapped traffic.
// ---------------------------------------------------------------------------
__global__ __launch_bounds__(256) void prefix_kernel(float* __restrict__ final_out) {
    const int tid = threadIdx.x;
    const int bh = blockIdx.x;
    float* base = g_CKV + (size_t)bh * NCHUNK * (DHEAD * DHEAD) + tid * 16;
    float run[16], cur[16], nxt[16];
#pragma unroll
    for (int j = 0; j < 16; j++) run[j] = 0.f;
#pragma unroll
    for (int q = 0; q < 4; q++) ((float4*)cur)[q] = ((float4*)base)[q];
    for (int n = 0; n < NCHUNK; n++) {
        float* p = base + (size_t)n * (DHEAD * DHEAD);
        if (n + 1 < NCHUNK) {
            const float* pn = p + DHEAD * DHEAD;
#pragma unroll
            for (int q = 0; q < 4; q++) ((float4*)nxt)[q] = ((const float4*)pn)[q];
        }
#pragma unroll
        for (int q = 0; q < 4; q++) ((float4*)p)[q] = ((float4*)run)[q];
#pragma unroll
        for (int j = 0; j < 16; j++) run[j] += cur[j];
#pragma unroll
        for (int j = 0; j < 16; j++) cur[j] = nxt[j];
    }
    float* fo = final_out + (size_t)bh * (DHEAD * DHEAD) + tid * 16;
#pragma unroll
    for (int q = 0; q < 4; q++) ((float4*)fo)[q] = ((float4*)run)[q];
}

// ---------------------------------------------------------------------------
// Per-chunk attention: out = tril(q@k^T)@v + q@prefix
// ---------------------------------------------------------------------------
#define KT_PITCH 68
#define ATTN_SMEM_FLOATS (4096 + CHUNK * KT_PITCH + 4096 + 4096)

__global__ __launch_bounds__(256) void attn_chunk_kernel() {
    extern __shared__ float smf[];
    float* qs = smf;
    float* kp = smf + 4096;
    float* vs = kp + CHUNK * KT_PITCH;
    float* ss = vs + 4096;

    const int tid = threadIdx.x;
    const int n = blockIdx.x & (NCHUNK - 1);
    const int bh = blockIdx.x >> 6;

    const float* qg = g_Q + ((size_t)bh * T_SEQ + n * CHUNK) * DHEAD;
    const float* kg = g_K + ((size_t)bh * T_SEQ + n * CHUNK) * DHEAD;
    const float* vg = g_V + ((size_t)bh * T_SEQ + n * CHUNK) * DHEAD;

    for (int f = tid; f < 1024; f += 256) {
        ((float4*)qs)[f] = ((const float4*)qg)[f];
        ((float4*)vs)[f] = ((const float4*)vg)[f];
        int j = f >> 4;
        int lq = (f & 15) << 2;
        float4 kv = ((const float4*)kg)[f];
        kp[(lq + 0) * KT_PITCH + j] = kv.x;
        kp[(lq + 1) * KT_PITCH + j] = kv.y;
        kp[(lq + 2) * KT_PITCH + j] = kv.z;
        kp[(lq + 3) * KT_PITCH + j] = kv.w;
    }
    __syncthreads();

    const int i0 = (tid >> 4) * 4;
    const int c0 = (tid & 15) * 4;

    {
        float sa[4][4] = {};
#pragma unroll 4
        for (int l = 0; l < DHEAD; l++) {
            float q4[4];
#pragma unroll
            for (int ii = 0; ii < 4; ii++) q4[ii] = qs[(i0 + ii) * DHEAD + l];
            float4 k4 = *(const float4*)&kp[l * KT_PITCH + c0];
#pragma unroll
            for (int ii = 0; ii < 4; ii++) {
                sa[ii][0] += q4[ii] * k4.x;
                sa[ii][1] += q4[ii] * k4.y;
                sa[ii][2] += q4[ii] * k4.z;
                sa[ii][3] += q4[ii] * k4.w;
            }
        }
#pragma unroll
        for (int ii = 0; ii < 4; ii++) {
            int i = i0 + ii;
#pragma unroll
            for (int jj = 0; jj < 4; jj++) {
                int j = c0 + jj;
                ss[i * CHUNK + j] = (j <= i) ? sa[ii][jj] : 0.f;
            }
        }
    }
    __syncthreads();

    {
        const float* pg = g_CKV + ((size_t)bh * NCHUNK + n) * (DHEAD * DHEAD);
        for (int f = tid; f < 1024; f += 256) ((float4*)kp)[f] = ((const float4*)pg)[f];
    }
    __syncthreads();

    {
        float oa[4][4] = {};
#pragma unroll 4
        for (int j = 0; j < CHUNK; j++) {
            float s4[4];
#pragma unroll
            for (int ii = 0; ii < 4; ii++) s4[ii] = ss[(i0 + ii) * CHUNK + j];
            float4 v4 = *(const float4*)&vs[j * DHEAD + c0];
#pragma unroll
            for (int ii = 0; ii < 4; ii++) {
                oa[ii][0] += s4[ii] * v4.x;
                oa[ii][1] += s4[ii] * v4.y;
                oa[ii][2] += s4[ii] * v4.z;
                oa[ii][3] += s4[ii] * v4.w;
            }
        }
#pragma unroll 4
        for (int k = 0; k < DHEAD; k++) {
            float q4[4];
#pragma unroll
            for (int ii = 0; ii < 4; ii++) q4[ii] = qs[(i0 + ii) * DHEAD + k];
            float4 p4 = *(const float4*)&kp[k * DHEAD + c0];
#pragma unroll
            for (int ii = 0; ii < 4; ii++) {
                oa[ii][0] += q4[ii] * p4.x;
                oa[ii][1] += q4[ii] * p4.y;
                oa[ii][2] += q4[ii] * p4.z;
                oa[ii][3] += q4[ii] * p4.w;
            }
        }
        float* og = g_O + ((size_t)bh * T_SEQ + n * CHUNK) * DHEAD;
#pragma unroll
        for (int ii = 0; ii < 4; ii++) {
            float4 o; o.x = oa[ii][0]; o.y = oa[ii][1]; o.z = oa[ii][2]; o.w = oa[ii][3];
            *(float4*)&og[(i0 + ii) * DHEAD + c0] = o;
        }
    }
}

// ---------------------------------------------------------------------------
extern "C" void kernel_launch(void* const* d_in, const int* in_sizes, int n_in,
                              void* d_out, int out_size) {
    const float* x     = (const float*)d_in[0];
    const float* w_qkv = (const float*)d_in[1];
    const float* w_o   = (const float*)d_in[2];
    float* out = (float*)d_out;

    const int M = in_sizes[0] / DMODEL;    // 8192
    const int BH = (M / T_SEQ) * NHEADS;   // 32

    cudaFuncSetAttribute(gemm_mma<0>, cudaFuncAttributeMaxDynamicSharedMemorySize, GEMM_SMEM);
    cudaFuncSetAttribute(gemm_mma<1>, cudaFuncAttributeMaxDynamicSharedMemorySize, GEMM_SMEM);
    cudaFuncSetAttribute(attn_chunk_kernel, cudaFuncAttributeMaxDynamicSharedMemorySize,
                         ATTN_SMEM_FLOATS * (int)sizeof(float));

    reset_cnt_kernel<<<1, 32>>>();
    split_kernel<<<(M * DMODEL) / 1024, 256>>>(x, M * DMODEL, 0);
    split_kernel<<<(3 * DMODEL * DMODEL) / 1024, 256>>>(w_qkv, 3 * DMODEL * DMODEL, 1);
    split_kernel<<<(DMODEL * DMODEL) / 1024, 256>>>(w_o, DMODEL * DMODEL, 2);

    dim3 g1(3 * DMODEL / 128, M / 128);
    gemm_mma<0><<<g1, 256, GEMM_SMEM>>>(nullptr);

    fixup_kernel<<<256, 256>>>(x, w_qkv);

    chunk_kv_kernel<<<BH * NCHUNK, 256>>>();
    prefix_kernel<<<BH, 256>>>(out + (size_t)M * DMODEL);
    attn_chunk_kernel<<<BH * NCHUNK, 256, ATTN_SMEM_FLOATS * (int)sizeof(float)>>>();

    split_kernel<<<(M * DMODEL) / 1024, 256>>>(nullptr, M * DMODEL, 3);
    dim3 g2(DMODEL / 128, M / 128);
    gemm_mma<1><<<g2, 256, GEMM_SMEM>>>(out);
}

// round 10
// speedup vs baseline: 1.2441x; 1.1262x over previous
#include <cuda_runtime.h>
#include <cuda_fp16.h>
#include <cstdint>

// Problem constants (fixed shapes per reference)
#define T_SEQ   4096
#define DMODEL  1024
#define NHEADS  16
#define DHEAD   64
#define CHUNK   64
#define NCHUNK  (T_SEQ / CHUNK)        // 64
#define QK_SCALE 0.125f                // 1/sqrt(64)
#define BATCH   2
#define MROWS   (BATCH * T_SEQ)        // 8192
#define FIX_TH  3e-3f
#define FIX_CAP (1 << 18)

// fp32 scratch
#define BHTD (BATCH * NHEADS * T_SEQ * DHEAD)
__device__ float g_Q[BHTD];
__device__ float g_K[BHTD];
__device__ float g_V[BHTD];
__device__ float g_CKV[BHTD];

// fp16 split scratch (h = fp16(x), m = fp16(x - h))
__device__ __half g_Xh[MROWS * DMODEL];
__device__ __half g_Xm[MROWS * DMODEL];
__device__ __half g_Wqh[3 * DMODEL * DMODEL];
__device__ __half g_Wqm[3 * DMODEL * DMODEL];
__device__ __half g_Woh[DMODEL * DMODEL];
__device__ __half g_Wom[DMODEL * DMODEL];
__device__ __half g_Oh[BHTD];
__device__ __half g_Om[BHTD];

// near-zero K/V fixup list
__device__ int g_fix_cnt;
__device__ int g_fix_idx[FIX_CAP];

// ---------------------------------------------------------------------------
// helpers
// ---------------------------------------------------------------------------
__device__ __forceinline__ uint32_t smem_u32(const void* p) {
    uint32_t a;
    asm("{ .reg .u64 t; cvta.to.shared.u64 t, %1; cvt.u32.u64 %0, t; }" : "=r"(a) : "l"(p));
    return a;
}
__device__ __forceinline__ void cp16(uint32_t dst, const void* src) {
    asm volatile("cp.async.cg.shared.global [%0], [%1], 16;" :: "r"(dst), "l"(src));
}
__device__ __forceinline__ void cp_commit() {
    asm volatile("cp.async.commit_group;");
}
__device__ __forceinline__ void cp_wait1() {
    asm volatile("cp.async.wait_group 1;" ::: "memory");
}
__device__ __forceinline__ void cp_wait0() {
    asm volatile("cp.async.wait_group 0;" ::: "memory");
}
__device__ __forceinline__ void ldmat4(uint32_t* r, uint32_t addr) {
    asm volatile("ldmatrix.sync.aligned.m8n8.x4.shared.b16 {%0,%1,%2,%3}, [%4];"
                 : "=r"(r[0]), "=r"(r[1]), "=r"(r[2]), "=r"(r[3]) : "r"(addr));
}
__device__ __forceinline__ void mma16816(float* c, const uint32_t* a, uint32_t b0, uint32_t b1) {
    asm volatile(
        "mma.sync.aligned.m16n8k16.row.col.f32.f16.f16.f32 "
        "{%0,%1,%2,%3}, {%4,%5,%6,%7}, {%8,%9}, {%0,%1,%2,%3};"
        : "+f"(c[0]), "+f"(c[1]), "+f"(c[2]), "+f"(c[3])
        : "r"(a[0]), "r"(a[1]), "r"(a[2]), "r"(a[3]), "r"(b0), "r"(b1));
}

// ---------------------------------------------------------------------------
// Split fp32 -> (h, m) fp16.  sel: 0=x, 1=w_qkv, 2=w_o
// ---------------------------------------------------------------------------
__global__ __launch_bounds__(256) void split_kernel(const float* __restrict__ src,
                                                    int n, int sel) {
    __half *hp, *mp;
    if (sel == 0)      { hp = g_Xh;  mp = g_Xm;  }
    else if (sel == 1) { hp = g_Wqh; mp = g_Wqm; }
    else               { hp = g_Woh; mp = g_Wom; }
    int i = (blockIdx.x * 256 + threadIdx.x) * 4;
    if (i >= n) return;
    float4 v = *(const float4*)(src + i);
    float xs[4] = {v.x, v.y, v.z, v.w};
    __align__(8) __half hb[4], mb[4];
#pragma unroll
    for (int j = 0; j < 4; j++) {
        __half h = __float2half_rn(xs[j]);
        float r = xs[j] - __half2float(h);
        hb[j] = h; mb[j] = __float2half_rn(r);
    }
    *(uint2*)(hp + i) = *(uint2*)hb;
    *(uint2*)(mp + i) = *(uint2*)mb;
}

__global__ void reset_cnt_kernel() { if (threadIdx.x == 0) g_fix_cnt = 0; }

// ---------------------------------------------------------------------------
// Split-fp16 HMMA GEMM. CTA tile 128x128, 8 warps (warp tile 64x32), K-chunks
// of 32, double-buffered cp.async (R5 configuration).
// MODE 0: QKV = X @ Wqkv^T.
//         Q tiles (bn<1024): 3 products (AhBh, AhBm, AmBh) -> scale, store.
//         K/V tiles:         2 products (AhBh, AhBm) -> binarize + flags
//                            (Am tile not even loaded).
// MODE 1: out = O(gathered) @ Wo^T, 3 products, plain store.
// ---------------------------------------------------------------------------
#define LDP     40                           // padded row pitch (elements)
#define TILE_E  (128 * LDP)                  // elements per tile
#define TILE_B2 (TILE_E * 2)                 // bytes per tile
#define STAGE_B (4 * TILE_B2)                // Ah, Am, Bh, Bm
#define GEMM_SMEM (2 * STAGE_B)              // 81920 bytes

template<int MODE>
__global__ __launch_bounds__(256) void gemm_mma(float* __restrict__ outp) {
    extern __shared__ __align__(128) char smc[];
    const uint32_t smb = smem_u32(smc);
    const int tid = threadIdx.x;
    const int wid = tid >> 5;
    const int lane = tid & 31;
    const int bn = blockIdx.x * 128;
    const int bm = blockIdx.y * 128;
    const int wm = wid & 1;      // 2 m-blocks of 64
    const int wn = wid >> 1;     // 4 n-blocks of 32
    const int nprod = (MODE == 0) ? ((bn >= 1024) ? 2 : 3) : 3;
    const bool needAm = (nprod == 3);

    // gmem source bases
    const __half *Ah, *Am, *Bh, *Bm;
    int bb = 0, tbase = 0;
    if (MODE == 0) {
        Ah = g_Xh + (size_t)bm * DMODEL;  Am = g_Xm + (size_t)bm * DMODEL;
        Bh = g_Wqh + (size_t)bn * DMODEL; Bm = g_Wqm + (size_t)bn * DMODEL;
    } else {
        bb = bm >> 12; tbase = bm & (T_SEQ - 1);
        Ah = g_Oh; Am = g_Om;
        Bh = g_Woh + (size_t)bn * DMODEL; Bm = g_Wom + (size_t)bn * DMODEL;
    }

    // per-thread gmem->smem slots: 2 cp16 per tile
    const int ldrow0 = tid >> 2;         // 0..63
    const int ldcq = tid & 3;            // 0..3 (8 fp16 each)

    auto load_stage = [&](int c, int st) {
        const int k0 = c * 32;
        const uint32_t stg = smb + (uint32_t)st * STAGE_B;
#pragma unroll
        for (int t = 0; t < 4; t++) {
            if (t == 1 && !needAm) continue;      // K/V tiles skip Am
            const __half* base;
            size_t roff; int rstride;
            if (MODE == 0 || t >= 2) {
                base = (t == 0) ? Ah : (t == 1) ? Am : (t == 2) ? Bh : Bm;
                roff = (size_t)k0 + ldcq * 8; rstride = DMODEL;
            } else {
                base = (t == 0) ? Ah : Am;
                int bh = bb * NHEADS + (k0 >> 6);
                roff = ((size_t)bh * T_SEQ + tbase) * DHEAD + (k0 & 63) + ldcq * 8;
                rstride = DHEAD;
            }
            const uint32_t tb = stg + (uint32_t)t * TILE_B2;
#pragma unroll
            for (int i = 0; i < 2; i++) {
                int row = ldrow0 + i * 64;
                cp16(tb + (uint32_t)(row * LDP + ldcq * 8) * 2,
                     base + roff + (size_t)row * rstride);
            }
        }
        cp_commit();
    };

    // ldmatrix lane address bases (relative element offsets within a tile)
    const int a_base = (wm * 64 + (lane & 15)) * LDP + (lane >> 4) * 8;
    const int b_base = (wn * 32 + (lane & 7) + (lane >> 4) * 8) * LDP + ((lane >> 3) & 1) * 8;

    float acc[4][4][4];
#pragma unroll
    for (int i = 0; i < 4; i++)
#pragma unroll
        for (int j = 0; j < 4; j++)
#pragma unroll
            for (int r = 0; r < 4; r++) acc[i][j][r] = 0.f;

    const int prodA[3] = {0, 0, 1};   // Ah, Ah, Am
    const int prodB[3] = {2, 3, 2};   // Bh, Bm, Bh

    load_stage(0, 0);
    const int NCH = DMODEL / 32;      // 32
    for (int c = 0; c < NCH; c++) {
        if (c + 1 < NCH) { load_stage(c + 1, (c + 1) & 1); cp_wait1(); }
        else cp_wait0();
        __syncthreads();
        const uint32_t stg = smb + (uint32_t)(c & 1) * STAGE_B;
        for (int p = 0; p < nprod; p++) {
            const uint32_t At = stg + (uint32_t)prodA[p] * TILE_B2;
            const uint32_t Bt = stg + (uint32_t)prodB[p] * TILE_B2;
#pragma unroll
            for (int s = 0; s < 2; s++) {
                uint32_t a[4][4], b[2][4];
#pragma unroll
                for (int mi = 0; mi < 4; mi++)
                    ldmat4(a[mi], At + (uint32_t)(a_base + mi * 16 * LDP + s * 16) * 2);
#pragma unroll
                for (int ni2 = 0; ni2 < 2; ni2++)
                    ldmat4(b[ni2], Bt + (uint32_t)(b_base + ni2 * 16 * LDP + s * 16) * 2);
#pragma unroll
                for (int mi = 0; mi < 4; mi++)
#pragma unroll
                    for (int ni = 0; ni < 4; ni++)
                        mma16816(acc[mi][ni], a[mi], b[ni >> 1][(ni & 1) * 2],
                                 b[ni >> 1][(ni & 1) * 2 + 1]);
            }
        }
        __syncthreads();
    }

    // epilogue: D frag (m16n8): c0,c1 row=lane>>2, cols 2*(lane&3)+{0,1}; c2,c3 row+8
    const int r0l = lane >> 2;
    const int cbl = (lane & 3) * 2;
#pragma unroll
    for (int mi = 0; mi < 4; mi++) {
#pragma unroll
        for (int ni = 0; ni < 4; ni++) {
#pragma unroll
            for (int half = 0; half < 2; half++) {
                int row = bm + wm * 64 + mi * 16 + r0l + half * 8;
                int col = bn + wn * 32 + ni * 8 + cbl;
                float v0 = acc[mi][ni][half * 2];
                float v1 = acc[mi][ni][half * 2 + 1];
                if (MODE == 0) {
                    int mb = row >> 12, t = row & (T_SEQ - 1);
                    int which = col >> 10, h = (col >> 6) & 15, l = col & 63;
                    size_t dst = (((size_t)(mb * NHEADS + h)) * T_SEQ + t) * DHEAD + l;
                    if (which == 0) {
                        float2 o; o.x = v0 * QK_SCALE; o.y = v1 * QK_SCALE;
                        *(float2*)(g_Q + dst) = o;
                    } else {
                        float* base = (which == 1) ? g_K : g_V;
                        float2 o;
                        o.x = (v0 >= 0.f) ? 1.f : -1.f;
                        o.y = (v1 >= 0.f) ? 1.f : -1.f;
                        *(float2*)(base + dst) = o;
                        if (fabsf(v0) < FIX_TH) {
                            int idx = atomicAdd(&g_fix_cnt, 1);
                            if (idx < FIX_CAP) g_fix_idx[idx] = row * 3072 + col;
                        }
                        if (fabsf(v1) < FIX_TH) {
                            int idx = atomicAdd(&g_fix_cnt, 1);
                            if (idx < FIX_CAP) g_fix_idx[idx] = row * 3072 + col + 1;
                        }
                    }
                } else {
                    float2 o; o.x = v0; o.y = v1;
                    *(float2*)(outp + (size_t)row * DMODEL + col) = o;
                }
            }
        }
    }
}

// ---------------------------------------------------------------------------
// Exact fp32 recompute of flagged near-zero K/V elements. One thread per
// element, STRICTLY SEQUENTIAL k-order FMA chain (matches the summation order
// that empirically reproduced the reference's signs in rounds 1 and 6-9).
// ---------------------------------------------------------------------------
__global__ __launch_bounds__(256) void fixup_kernel(const float* __restrict__ x,
                                                    const float* __restrict__ w) {
    int cnt = g_fix_cnt; if (cnt > FIX_CAP) cnt = FIX_CAP;
    const int stride = gridDim.x * blockDim.x;
    for (int i = blockIdx.x * blockDim.x + threadIdx.x; i < cnt; i += stride) {
        int code = g_fix_idx[i];
        int m = code / 3072, n = code % 3072;
        const float4* xr = (const float4*)(x + (size_t)m * DMODEL);
        const float4* wr = (const float4*)(w + (size_t)n * DMODEL);
        float acc = 0.f;
#pragma unroll 4
        for (int j = 0; j < DMODEL / 4; j++) {
            float4 a = xr[j], b = wr[j];
            acc = fmaf(a.x, b.x, acc);
            acc = fmaf(a.y, b.y, acc);
            acc = fmaf(a.z, b.z, acc);
            acc = fmaf(a.w, b.w, acc);
        }
        int mb = m >> 12, t = m & (T_SEQ - 1);
        int h = (n >> 6) & 15, l = n & 63;
        float* base = ((n >> 10) == 1) ? g_K : g_V;
        base[(((size_t)(mb * NHEADS + h)) * T_SEQ + t) * DHEAD + l] = (acc >= 0.f) ? 1.f : -1.f;
    }
}

// ---------------------------------------------------------------------------
// chunk_kv[bh][n][k][v] = sum_t kc[t][k] * vc[t][v]
// ---------------------------------------------------------------------------
__global__ __launch_bounds__(256) void chunk_kv_kernel() {
    __shared__ float ks[CHUNK * DHEAD];
    __shared__ float vs[CHUNK * DHEAD];
    const int tid = threadIdx.x;
    const int n = blockIdx.x & (NCHUNK - 1);
    const int bh = blockIdx.x >> 6;
    const float* kg = g_K + ((size_t)bh * T_SEQ + n * CHUNK) * DHEAD;
    const float* vg = g_V + ((size_t)bh * T_SEQ + n * CHUNK) * DHEAD;
    for (int f = tid; f < 1024; f += 256) {
        ((float4*)ks)[f] = ((const float4*)kg)[f];
        ((float4*)vs)[f] = ((const float4*)vg)[f];
    }
    __syncthreads();
    const int kk0 = (tid >> 4) * 4;
    const int vv0 = (tid & 15) * 4;
    float acc[4][4] = {};
#pragma unroll 4
    for (int t = 0; t < CHUNK; t++) {
        float kv[4];
        *(float4*)kv = *(const float4*)&ks[t * DHEAD + kk0];
        float4 v4 = *(const float4*)&vs[t * DHEAD + vv0];
#pragma unroll
        for (int ii = 0; ii < 4; ii++) {
            acc[ii][0] += kv[ii] * v4.x;
            acc[ii][1] += kv[ii] * v4.y;
            acc[ii][2] += kv[ii] * v4.z;
            acc[ii][3] += kv[ii] * v4.w;
        }
    }
    float* cg = g_CKV + ((size_t)bh * NCHUNK + n) * (DHEAD * DHEAD);
#pragma unroll
    for (int ii = 0; ii < 4; ii++) {
        float4 o; o.x = acc[ii][0]; o.y = acc[ii][1]; o.z = acc[ii][2]; o.w = acc[ii][3];
        *(float4*)&cg[(kk0 + ii) * DHEAD + vv0] = o;
    }
}

// ---------------------------------------------------------------------------
// In-place exclusive prefix over chunks; writes final_state. (R5 simple form)
// ---------------------------------------------------------------------------
__global__ __launch_bounds__(256) void prefix_kernel(float* __restrict__ final_out) {
    const int tid = threadIdx.x;
    const int bh = blockIdx.x;
    float run[16];
#pragma unroll
    for (int j = 0; j < 16; j++) run[j] = 0.f;
    for (int n = 0; n < NCHUNK; n++) {
        float* p = g_CKV + ((size_t)bh * NCHUNK + n) * (DHEAD * DHEAD) + tid * 16;
        float tmp[16];
#pragma unroll
        for (int q = 0; q < 4; q++) ((float4*)tmp)[q] = ((float4*)p)[q];
#pragma unroll
        for (int q = 0; q < 4; q++) ((float4*)p)[q] = ((float4*)run)[q];
#pragma unroll
        for (int j = 0; j < 16; j++) run[j] += tmp[j];
    }
    float* fo = final_out + (size_t)bh * (DHEAD * DHEAD) + tid * 16;
#pragma unroll
    for (int q = 0; q < 4; q++) ((float4*)fo)[q] = ((float4*)run)[q];
}

// ---------------------------------------------------------------------------
// Per-chunk attention: out = tril(q@k^T)@v + q@prefix
// Epilogue writes the fp16 (h,m) split of the output directly (fused split).
// ---------------------------------------------------------------------------
#define KT_PITCH 68
#define ATTN_SMEM_FLOATS (4096 + CHUNK * KT_PITCH + 4096 + 4096)

__global__ __launch_bounds__(256) void attn_chunk_kernel() {
    extern __shared__ float smf[];
    float* qs = smf;
    float* kp = smf + 4096;
    float* vs = kp + CHUNK * KT_PITCH;
    float* ss = vs + 4096;

    const int tid = threadIdx.x;
    const int n = blockIdx.x & (NCHUNK - 1);
    const int bh = blockIdx.x >> 6;

    const float* qg = g_Q + ((size_t)bh * T_SEQ + n * CHUNK) * DHEAD;
    const float* kg = g_K + ((size_t)bh * T_SEQ + n * CHUNK) * DHEAD;
    const float* vg = g_V + ((size_t)bh * T_SEQ + n * CHUNK) * DHEAD;

    for (int f = tid; f < 1024; f += 256) {
        ((float4*)qs)[f] = ((const float4*)qg)[f];
        ((float4*)vs)[f] = ((const float4*)vg)[f];
        int j = f >> 4;
        int lq = (f & 15) << 2;
        float4 kv = ((const float4*)kg)[f];
        kp[(lq + 0) * KT_PITCH + j] = kv.x;
        kp[(lq + 1) * KT_PITCH + j] = kv.y;
        kp[(lq + 2) * KT_PITCH + j] = kv.z;
        kp[(lq + 3) * KT_PITCH + j] = kv.w;
    }
    __syncthreads();

    const int i0 = (tid >> 4) * 4;
    const int c0 = (tid & 15) * 4;

    {
        float sa[4][4] = {};
#pragma unroll 4
        for (int l = 0; l < DHEAD; l++) {
            float q4[4];
#pragma unroll
            for (int ii = 0; ii < 4; ii++) q4[ii] = qs[(i0 + ii) * DHEAD + l];
            float4 k4 = *(const float4*)&kp[l * KT_PITCH + c0];
#pragma unroll
            for (int ii = 0; ii < 4; ii++) {
                sa[ii][0] += q4[ii] * k4.x;
                sa[ii][1] += q4[ii] * k4.y;
                sa[ii][2] += q4[ii] * k4.z;
                sa[ii][3] += q4[ii] * k4.w;
            }
        }
#pragma unroll
        for (int ii = 0; ii < 4; ii++) {
            int i = i0 + ii;
#pragma unroll
            for (int jj = 0; jj < 4; jj++) {
                int j = c0 + jj;
                ss[i * CHUNK + j] = (j <= i) ? sa[ii][jj] : 0.f;
            }
        }
    }
    __syncthreads();

    {
        const float* pg = g_CKV + ((size_t)bh * NCHUNK + n) * (DHEAD * DHEAD);
        for (int f = tid; f < 1024; f += 256) ((float4*)kp)[f] = ((const float4*)pg)[f];
    }
    __syncthreads();

    {
        float oa[4][4] = {};
#pragma unroll 4
        for (int j = 0; j < CHUNK; j++) {
            float s4[4];
#pragma unroll
            for (int ii = 0; ii < 4; ii++) s4[ii] = ss[(i0 + ii) * CHUNK + j];
            float4 v4 = *(const float4*)&vs[j * DHEAD + c0];
#pragma unroll
            for (int ii = 0; ii < 4; ii++) {
                oa[ii][0] += s4[ii] * v4.x;
                oa[ii][1] += s4[ii] * v4.y;
                oa[ii][2] += s4[ii] * v4.z;
                oa[ii][3] += s4[ii] * v4.w;
            }
        }
#pragma unroll 4
        for (int k = 0; k < DHEAD; k++) {
            float q4[4];
#pragma unroll
            for (int ii = 0; ii < 4; ii++) q4[ii] = qs[(i0 + ii) * DHEAD + k];
            float4 p4 = *(const float4*)&kp[k * DHEAD + c0];
#pragma unroll
            for (int ii = 0; ii < 4; ii++) {
                oa[ii][0] += q4[ii] * p4.x;
                oa[ii][1] += q4[ii] * p4.y;
                oa[ii][2] += q4[ii] * p4.z;
                oa[ii][3] += q4[ii] * p4.w;
            }
        }
        // fused fp16 (h, m) split store
        __half* ohg = g_Oh + ((size_t)bh * T_SEQ + n * CHUNK) * DHEAD;
        __half* omg = g_Om + ((size_t)bh * T_SEQ + n * CHUNK) * DHEAD;
#pragma unroll
        for (int ii = 0; ii < 4; ii++) {
            __align__(8) __half hb[4], mb[4];
#pragma unroll
            for (int jj = 0; jj < 4; jj++) {
                float v = oa[ii][jj];
                __half h = __float2half_rn(v);
                hb[jj] = h;
                mb[jj] = __float2half_rn(v - __half2float(h));
            }
            *(uint2*)(ohg + (i0 + ii) * DHEAD + c0) = *(uint2*)hb;
            *(uint2*)(omg + (i0 + ii) * DHEAD + c0) = *(uint2*)mb;
        }
    }
}

// ---------------------------------------------------------------------------
extern "C" void kernel_launch(void* const* d_in, const int* in_sizes, int n_in,
                              void* d_out, int out_size) {
    const float* x     = (const float*)d_in[0];
    const float* w_qkv = (const float*)d_in[1];
    const float* w_o   = (const float*)d_in[2];
    float* out = (float*)d_out;

    const int M = in_sizes[0] / DMODEL;    // 8192
    const int BH = (M / T_SEQ) * NHEADS;   // 32

    cudaFuncSetAttribute(gemm_mma<0>, cudaFuncAttributeMaxDynamicSharedMemorySize, GEMM_SMEM);
    cudaFuncSetAttribute(gemm_mma<1>, cudaFuncAttributeMaxDynamicSharedMemorySize, GEMM_SMEM);
    cudaFuncSetAttribute(attn_chunk_kernel, cudaFuncAttributeMaxDynamicSharedMemorySize,
                         ATTN_SMEM_FLOATS * (int)sizeof(float));

    reset_cnt_kernel<<<1, 32>>>();
    split_kernel<<<(M * DMODEL) / 1024, 256>>>(x, M * DMODEL, 0);
    split_kernel<<<(3 * DMODEL * DMODEL) / 1024, 256>>>(w_qkv, 3 * DMODEL * DMODEL, 1);
    split_kernel<<<(DMODEL * DMODEL) / 1024, 256>>>(w_o, DMODEL * DMODEL, 2);

    dim3 g1(3 * DMODEL / 128, M / 128);
    gemm_mma<0><<<g1, 256, GEMM_SMEM>>>(nullptr);

    fixup_kernel<<<256, 256>>>(x, w_qkv);

    chunk_kv_kernel<<<BH * NCHUNK, 256>>>();
    prefix_kernel<<<BH, 256>>>(out + (size_t)M * DMODEL);
    attn_chunk_kernel<<<BH * NCHUNK, 256, ATTN_SMEM_FLOATS * (int)sizeof(float)>>>();

    dim3 g2(DMODEL / 128, M / 128);
    gemm_mma<1><<<g2, 256, GEMM_SMEM>>>(out);
}

// round 11
// speedup vs baseline: 1.3071x; 1.0507x over previous
#include <cuda_runtime.h>
#include <cuda_fp16.h>
#include <cstdint>

// Problem constants (fixed shapes per reference)
#define T_SEQ   4096
#define DMODEL  1024
#define NHEADS  16
#define DHEAD   64
#define CHUNK   64
#define NCHUNK  (T_SEQ / CHUNK)        // 64
#define QK_SCALE 0.125f                // 1/sqrt(64)
#define BATCH   2
#define MROWS   (BATCH * T_SEQ)        // 8192
#define FIX_TH  3e-3f
#define FIX_CAP (1 << 18)

// fp32 scratch
#define BHTD (BATCH * NHEADS * T_SEQ * DHEAD)
__device__ float g_Q[BHTD];
__device__ float g_K[BHTD];
__device__ float g_V[BHTD];
__device__ float g_CKV[BHTD];

// fp16 split scratch (h = fp16(x), m = fp16(x - h))
__device__ __half g_Xh[MROWS * DMODEL];
__device__ __half g_Xm[MROWS * DMODEL];
__device__ __half g_Wqh[3 * DMODEL * DMODEL];
__device__ __half g_Wqm[3 * DMODEL * DMODEL];
__device__ __half g_Woh[DMODEL * DMODEL];
__device__ __half g_Wom[DMODEL * DMODEL];
__device__ __half g_Oh[BHTD];
__device__ __half g_Om[BHTD];

// near-zero K/V fixup list
__device__ int g_fix_cnt;
__device__ int g_fix_idx[FIX_CAP];

// ---------------------------------------------------------------------------
// helpers
// ---------------------------------------------------------------------------
__device__ __forceinline__ uint32_t smem_u32(const void* p) {
    uint32_t a;
    asm("{ .reg .u64 t; cvta.to.shared.u64 t, %1; cvt.u32.u64 %0, t; }" : "=r"(a) : "l"(p));
    return a;
}
__device__ __forceinline__ void cp16(uint32_t dst, const void* src) {
    asm volatile("cp.async.cg.shared.global [%0], [%1], 16;" :: "r"(dst), "l"(src));
}
__device__ __forceinline__ void cp_commit() {
    asm volatile("cp.async.commit_group;");
}
__device__ __forceinline__ void cp_wait1() {
    asm volatile("cp.async.wait_group 1;" ::: "memory");
}
__device__ __forceinline__ void cp_wait0() {
    asm volatile("cp.async.wait_group 0;" ::: "memory");
}
__device__ __forceinline__ void ldmat4(uint32_t* r, uint32_t addr) {
    asm volatile("ldmatrix.sync.aligned.m8n8.x4.shared.b16 {%0,%1,%2,%3}, [%4];"
                 : "=r"(r[0]), "=r"(r[1]), "=r"(r[2]), "=r"(r[3]) : "r"(addr));
}
__device__ __forceinline__ void mma16816(float* c, const uint32_t* a, uint32_t b0, uint32_t b1) {
    asm volatile(
        "mma.sync.aligned.m16n8k16.row.col.f32.f16.f16.f32 "
        "{%0,%1,%2,%3}, {%4,%5,%6,%7}, {%8,%9}, {%0,%1,%2,%3};"
        : "+f"(c[0]), "+f"(c[1]), "+f"(c[2]), "+f"(c[3])
        : "r"(a[0]), "r"(a[1]), "r"(a[2]), "r"(a[3]), "r"(b0), "r"(b1));
}

// ---------------------------------------------------------------------------
// Split fp32 -> (h, m) fp16.  sel: 0=x, 1=w_qkv, 2=w_o
// ---------------------------------------------------------------------------
__global__ __launch_bounds__(256) void split_kernel(const float* __restrict__ src,
                                                    int n, int sel) {
    __half *hp, *mp;
    if (sel == 0)      { hp = g_Xh;  mp = g_Xm;  }
    else if (sel == 1) { hp = g_Wqh; mp = g_Wqm; }
    else               { hp = g_Woh; mp = g_Wom; }
    int i = (blockIdx.x * 256 + threadIdx.x) * 4;
    if (i >= n) return;
    float4 v = *(const float4*)(src + i);
    float xs[4] = {v.x, v.y, v.z, v.w};
    __align__(8) __half hb[4], mb[4];
#pragma unroll
    for (int j = 0; j < 4; j++) {
        __half h = __float2half_rn(xs[j]);
        float r = xs[j] - __half2float(h);
        hb[j] = h; mb[j] = __float2half_rn(r);
    }
    *(uint2*)(hp + i) = *(uint2*)hb;
    *(uint2*)(mp + i) = *(uint2*)mb;
}

__global__ void reset_cnt_kernel() { if (threadIdx.x == 0) g_fix_cnt = 0; }

// ---------------------------------------------------------------------------
// Split-fp16 HMMA GEMM. CTA tile 128x128, 8 warps (warp tile 64x32), K-chunks
// of 32, double-buffered cp.async (R5 configuration).
// MODE 0: QKV = X @ Wqkv^T.
//         Q tiles (bn<1024): 3 products (AhBh, AhBm, AmBh) -> scale, store.
//         K/V tiles:         1 product  (AhBh) -> binarize + near-zero flags
//                            (only Ah and Bh tiles loaded).
// MODE 1: out = O(gathered) @ Wo^T, 3 products, plain store.
// ---------------------------------------------------------------------------
#define LDP     40                           // padded row pitch (elements)
#define TILE_E  (128 * LDP)                  // elements per tile
#define TILE_B2 (TILE_E * 2)                 // bytes per tile
#define STAGE_B (4 * TILE_B2)                // Ah, Am, Bh, Bm
#define GEMM_SMEM (2 * STAGE_B)              // 81920 bytes

template<int MODE>
__global__ __launch_bounds__(256) void gemm_mma(float* __restrict__ outp) {
    extern __shared__ __align__(128) char smc[];
    const uint32_t smb = smem_u32(smc);
    const int tid = threadIdx.x;
    const int wid = tid >> 5;
    const int lane = tid & 31;
    const int bn = blockIdx.x * 128;
    const int bm = blockIdx.y * 128;
    const int wm = wid & 1;      // 2 m-blocks of 64
    const int wn = wid >> 1;     // 4 n-blocks of 32
    const int nprod = (MODE == 0) ? ((bn >= 1024) ? 1 : 3) : 3;
    const bool needM = (nprod == 3);     // Am/Bm tiles needed?

    // gmem source bases
    const __half *Ah, *Am, *Bh, *Bm;
    int bb = 0, tbase = 0;
    if (MODE == 0) {
        Ah = g_Xh + (size_t)bm * DMODEL;  Am = g_Xm + (size_t)bm * DMODEL;
        Bh = g_Wqh + (size_t)bn * DMODEL; Bm = g_Wqm + (size_t)bn * DMODEL;
    } else {
        bb = bm >> 12; tbase = bm & (T_SEQ - 1);
        Ah = g_Oh; Am = g_Om;
        Bh = g_Woh + (size_t)bn * DMODEL; Bm = g_Wom + (size_t)bn * DMODEL;
    }

    // per-thread gmem->smem slots: 2 cp16 per tile
    const int ldrow0 = tid >> 2;         // 0..63
    const int ldcq = tid & 3;            // 0..3 (8 fp16 each)

    auto load_stage = [&](int c, int st) {
        const int k0 = c * 32;
        const uint32_t stg = smb + (uint32_t)st * STAGE_B;
#pragma unroll
        for (int t = 0; t < 4; t++) {
            if ((t == 1 || t == 3) && !needM) continue;  // KV tiles: only h
            const __half* base;
            size_t roff; int rstride;
            if (MODE == 0 || t >= 2) {
                base = (t == 0) ? Ah : (t == 1) ? Am : (t == 2) ? Bh : Bm;
                roff = (size_t)k0 + ldcq * 8; rstride = DMODEL;
            } else {
                base = (t == 0) ? Ah : Am;
                int bh = bb * NHEADS + (k0 >> 6);
                roff = ((size_t)bh * T_SEQ + tbase) * DHEAD + (k0 & 63) + ldcq * 8;
                rstride = DHEAD;
            }
            const uint32_t tb = stg + (uint32_t)t * TILE_B2;
#pragma unroll
            for (int i = 0; i < 2; i++) {
                int row = ldrow0 + i * 64;
                cp16(tb + (uint32_t)(row * LDP + ldcq * 8) * 2,
                     base + roff + (size_t)row * rstride);
            }
        }
        cp_commit();
    };

    // ldmatrix lane address bases (relative element offsets within a tile)
    const int a_base = (wm * 64 + (lane & 15)) * LDP + (lane >> 4) * 8;
    const int b_base = (wn * 32 + (lane & 7) + (lane >> 4) * 8) * LDP + ((lane >> 3) & 1) * 8;

    float acc[4][4][4];
#pragma unroll
    for (int i = 0; i < 4; i++)
#pragma unroll
        for (int j = 0; j < 4; j++)
#pragma unroll
            for (int r = 0; r < 4; r++) acc[i][j][r] = 0.f;

    const int prodA[3] = {0, 0, 1};   // Ah, Ah, Am
    const int prodB[3] = {2, 3, 2};   // Bh, Bm, Bh

    load_stage(0, 0);
    const int NCH = DMODEL / 32;      // 32
    for (int c = 0; c < NCH; c++) {
        if (c + 1 < NCH) { load_stage(c + 1, (c + 1) & 1); cp_wait1(); }
        else cp_wait0();
        __syncthreads();
        const uint32_t stg = smb + (uint32_t)(c & 1) * STAGE_B;
        for (int p = 0; p < nprod; p++) {
            const uint32_t At = stg + (uint32_t)prodA[p] * TILE_B2;
            const uint32_t Bt = stg + (uint32_t)prodB[p] * TILE_B2;
#pragma unroll
            for (int s = 0; s < 2; s++) {
                uint32_t a[4][4], b[2][4];
#pragma unroll
                for (int mi = 0; mi < 4; mi++)
                    ldmat4(a[mi], At + (uint32_t)(a_base + mi * 16 * LDP + s * 16) * 2);
#pragma unroll
                for (int ni2 = 0; ni2 < 2; ni2++)
                    ldmat4(b[ni2], Bt + (uint32_t)(b_base + ni2 * 16 * LDP + s * 16) * 2);
#pragma unroll
                for (int mi = 0; mi < 4; mi++)
#pragma unroll
                    for (int ni = 0; ni < 4; ni++)
                        mma16816(acc[mi][ni], a[mi], b[ni >> 1][(ni & 1) * 2],
                                 b[ni >> 1][(ni & 1) * 2 + 1]);
            }
        }
        __syncthreads();
    }

    // epilogue: D frag (m16n8): c0,c1 row=lane>>2, cols 2*(lane&3)+{0,1}; c2,c3 row+8
    const int r0l = lane >> 2;
    const int cbl = (lane & 3) * 2;
#pragma unroll
    for (int mi = 0; mi < 4; mi++) {
#pragma unroll
        for (int ni = 0; ni < 4; ni++) {
#pragma unroll
            for (int half = 0; half < 2; half++) {
                int row = bm + wm * 64 + mi * 16 + r0l + half * 8;
                int col = bn + wn * 32 + ni * 8 + cbl;
                float v0 = acc[mi][ni][half * 2];
                float v1 = acc[mi][ni][half * 2 + 1];
                if (MODE == 0) {
                    int mb = row >> 12, t = row & (T_SEQ - 1);
                    int which = col >> 10, h = (col >> 6) & 15, l = col & 63;
                    size_t dst = (((size_t)(mb * NHEADS + h)) * T_SEQ + t) * DHEAD + l;
                    if (which == 0) {
                        float2 o; o.x = v0 * QK_SCALE; o.y = v1 * QK_SCALE;
                        *(float2*)(g_Q + dst) = o;
                    } else {
                        float* base = (which == 1) ? g_K : g_V;
                        float2 o;
                        o.x = (v0 >= 0.f) ? 1.f : -1.f;
                        o.y = (v1 >= 0.f) ? 1.f : -1.f;
                        *(float2*)(base + dst) = o;
                        if (fabsf(v0) < FIX_TH) {
                            int idx = atomicAdd(&g_fix_cnt, 1);
                            if (idx < FIX_CAP) g_fix_idx[idx] = row * 3072 + col;
                        }
                        if (fabsf(v1) < FIX_TH) {
                            int idx = atomicAdd(&g_fix_cnt, 1);
                            if (idx < FIX_CAP) g_fix_idx[idx] = row * 3072 + col + 1;
                        }
                    }
                } else {
                    float2 o; o.x = v0; o.y = v1;
                    *(float2*)(outp + (size_t)row * DMODEL + col) = o;
                }
            }
        }
    }
}

// ---------------------------------------------------------------------------
// Exact fp32 recompute of flagged near-zero K/V elements. One thread per
// element, STRICTLY SEQUENTIAL k-order FMA chain (matches the summation order
// that empirically reproduced the reference's signs in rounds 1 and 6-10).
// ---------------------------------------------------------------------------
__global__ __launch_bounds__(256) void fixup_kernel(const float* __restrict__ x,
                                                    const float* __restrict__ w) {
    int cnt = g_fix_cnt; if (cnt > FIX_CAP) cnt = FIX_CAP;
    const int stride = gridDim.x * blockDim.x;
    for (int i = blockIdx.x * blockDim.x + threadIdx.x; i < cnt; i += stride) {
        int code = g_fix_idx[i];
        int m = code / 3072, n = code % 3072;
        const float4* xr = (const float4*)(x + (size_t)m * DMODEL);
        const float4* wr = (const float4*)(w + (size_t)n * DMODEL);
        float acc = 0.f;
#pragma unroll 4
        for (int j = 0; j < DMODEL / 4; j++) {
            float4 a = xr[j], b = wr[j];
            acc = fmaf(a.x, b.x, acc);
            acc = fmaf(a.y, b.y, acc);
            acc = fmaf(a.z, b.z, acc);
            acc = fmaf(a.w, b.w, acc);
        }
        int mb = m >> 12, t = m & (T_SEQ - 1);
        int h = (n >> 6) & 15, l = n & 63;
        float* base = ((n >> 10) == 1) ? g_K : g_V;
        base[(((size_t)(mb * NHEADS + h)) * T_SEQ + t) * DHEAD + l] = (acc >= 0.f) ? 1.f : -1.f;
    }
}

// ---------------------------------------------------------------------------
// chunk_kv[bh][n][k][v] = sum_t kc[t][k] * vc[t][v]
// ---------------------------------------------------------------------------
__global__ __launch_bounds__(256) void chunk_kv_kernel() {
    __shared__ float ks[CHUNK * DHEAD];
    __shared__ float vs[CHUNK * DHEAD];
    const int tid = threadIdx.x;
    const int n = blockIdx.x & (NCHUNK - 1);
    const int bh = blockIdx.x >> 6;
    const float* kg = g_K + ((size_t)bh * T_SEQ + n * CHUNK) * DHEAD;
    const float* vg = g_V + ((size_t)bh * T_SEQ + n * CHUNK) * DHEAD;
    for (int f = tid; f < 1024; f += 256) {
        ((float4*)ks)[f] = ((const float4*)kg)[f];
        ((float4*)vs)[f] = ((const float4*)vg)[f];
    }
    __syncthreads();
    const int kk0 = (tid >> 4) * 4;
    const int vv0 = (tid & 15) * 4;
    float acc[4][4] = {};
#pragma unroll 4
    for (int t = 0; t < CHUNK; t++) {
        float kv[4];
        *(float4*)kv = *(const float4*)&ks[t * DHEAD + kk0];
        float4 v4 = *(const float4*)&vs[t * DHEAD + vv0];
#pragma unroll
        for (int ii = 0; ii < 4; ii++) {
            acc[ii][0] += kv[ii] * v4.x;
            acc[ii][1] += kv[ii] * v4.y;
            acc[ii][2] += kv[ii] * v4.z;
            acc[ii][3] += kv[ii] * v4.w;
        }
    }
    float* cg = g_CKV + ((size_t)bh * NCHUNK + n) * (DHEAD * DHEAD);
#pragma unroll
    for (int ii = 0; ii < 4; ii++) {
        float4 o; o.x = acc[ii][0]; o.y = acc[ii][1]; o.z = acc[ii][2]; o.w = acc[ii][3];
        *(float4*)&cg[(kk0 + ii) * DHEAD + vv0] = o;
    }
}

// ---------------------------------------------------------------------------
// In-place exclusive prefix over chunks; writes final_state. (R5 simple form)
// ---------------------------------------------------------------------------
__global__ __launch_bounds__(256) void prefix_kernel(float* __restrict__ final_out) {
    const int tid = threadIdx.x;
    const int bh = blockIdx.x;
    float run[16];
#pragma unroll
    for (int j = 0; j < 16; j++) run[j] = 0.f;
    for (int n = 0; n < NCHUNK; n++) {
        float* p = g_CKV + ((size_t)bh * NCHUNK + n) * (DHEAD * DHEAD) + tid * 16;
        float tmp[16];
#pragma unroll
        for (int q = 0; q < 4; q++) ((float4*)tmp)[q] = ((float4*)p)[q];
#pragma unroll
        for (int q = 0; q < 4; q++) ((float4*)p)[q] = ((float4*)run)[q];
#pragma unroll
        for (int j = 0; j < 16; j++) run[j] += tmp[j];
    }
    float* fo = final_out + (size_t)bh * (DHEAD * DHEAD) + tid * 16;
#pragma unroll
    for (int q = 0; q < 4; q++) ((float4*)fo)[q] = ((float4*)run)[q];
}

// ---------------------------------------------------------------------------
// Per-chunk attention: out = tril(q@k^T)@v + q@prefix
// Epilogue writes the fp16 (h,m) split of the output directly (fused split).
// ---------------------------------------------------------------------------
#define KT_PITCH 68
#define ATTN_SMEM_FLOATS (4096 + CHUNK * KT_PITCH + 4096 + 4096)

__global__ __launch_bounds__(256) void attn_chunk_kernel() {
    extern __shared__ float smf[];
    float* qs = smf;
    float* kp = smf + 4096;
    float* vs = kp + CHUNK * KT_PITCH;
    float* ss = vs + 4096;

    const int tid = threadIdx.x;
    const int n = blockIdx.x & (NCHUNK - 1);
    const int bh = blockIdx.x >> 6;

    const float* qg = g_Q + ((size_t)bh * T_SEQ + n * CHUNK) * DHEAD;
    const float* kg = g_K + ((size_t)bh * T_SEQ + n * CHUNK) * DHEAD;
    const float* vg = g_V + ((size_t)bh * T_SEQ + n * CHUNK) * DHEAD;

    for (int f = tid; f < 1024; f += 256) {
        ((float4*)qs)[f] = ((const float4*)qg)[f];
        ((float4*)vs)[f] = ((const float4*)vg)[f];
        int j = f >> 4;
        int lq = (f & 15) << 2;
        float4 kv = ((const float4*)kg)[f];
        kp[(lq + 0) * KT_PITCH + j] = kv.x;
        kp[(lq + 1) * KT_PITCH + j] = kv.y;
        kp[(lq + 2) * KT_PITCH + j] = kv.z;
        kp[(lq + 3) * KT_PITCH + j] = kv.w;
    }
    __syncthreads();

    const int i0 = (tid >> 4) * 4;
    const int c0 = (tid & 15) * 4;

    {
        float sa[4][4] = {};
#pragma unroll 4
        for (int l = 0; l < DHEAD; l++) {
            float q4[4];
#pragma unroll
            for (int ii = 0; ii < 4; ii++) q4[ii] = qs[(i0 + ii) * DHEAD + l];
            float4 k4 = *(const float4*)&kp[l * KT_PITCH + c0];
#pragma unroll
            for (int ii = 0; ii < 4; ii++) {
                sa[ii][0] += q4[ii] * k4.x;
                sa[ii][1] += q4[ii] * k4.y;
                sa[ii][2] += q4[ii] * k4.z;
                sa[ii][3] += q4[ii] * k4.w;
            }
        }
#pragma unroll
        for (int ii = 0; ii < 4; ii++) {
            int i = i0 + ii;
#pragma unroll
            for (int jj = 0; jj < 4; jj++) {
                int j = c0 + jj;
                ss[i * CHUNK + j] = (j <= i) ? sa[ii][jj] : 0.f;
            }
        }
    }
    __syncthreads();

    {
        const float* pg = g_CKV + ((size_t)bh * NCHUNK + n) * (DHEAD * DHEAD);
        for (int f = tid; f < 1024; f += 256) ((float4*)kp)[f] = ((const float4*)pg)[f];
    }
    __syncthreads();

    {
        float oa[4][4] = {};
#pragma unroll 4
        for (int j = 0; j < CHUNK; j++) {
            float s4[4];
#pragma unroll
            for (int ii = 0; ii < 4; ii++) s4[ii] = ss[(i0 + ii) * CHUNK + j];
            float4 v4 = *(const float4*)&vs[j * DHEAD + c0];
#pragma unroll
            for (int ii = 0; ii < 4; ii++) {
                oa[ii][0] += s4[ii] * v4.x;
                oa[ii][1] += s4[ii] * v4.y;
                oa[ii][2] += s4[ii] * v4.z;
                oa[ii][3] += s4[ii] * v4.w;
            }
        }
#pragma unroll 4
        for (int k = 0; k < DHEAD; k++) {
            float q4[4];
#pragma unroll
            for (int ii = 0; ii < 4; ii++) q4[ii] = qs[(i0 + ii) * DHEAD + k];
            float4 p4 = *(const float4*)&kp[k * DHEAD + c0];
#pragma unroll
            for (int ii = 0; ii < 4; ii++) {
                oa[ii][0] += q4[ii] * p4.x;
                oa[ii][1] += q4[ii] * p4.y;
                oa[ii][2] += q4[ii] * p4.z;
                oa[ii][3] += q4[ii] * p4.w;
            }
        }
        // fused fp16 (h, m) split store
        __half* ohg = g_Oh + ((size_t)bh * T_SEQ + n * CHUNK) * DHEAD;
        __half* omg = g_Om + ((size_t)bh * T_SEQ + n * CHUNK) * DHEAD;
#pragma unroll
        for (int ii = 0; ii < 4; ii++) {
            __align__(8) __half hb[4], mb[4];
#pragma unroll
            for (int jj = 0; jj < 4; jj++) {
                float v = oa[ii][jj];
                __half h = __float2half_rn(v);
                hb[jj] = h;
                mb[jj] = __float2half_rn(v - __half2float(h));
            }
            *(uint2*)(ohg + (i0 + ii) * DHEAD + c0) = *(uint2*)hb;
            *(uint2*)(omg + (i0 + ii) * DHEAD + c0) = *(uint2*)mb;
        }
    }
}

// ---------------------------------------------------------------------------
extern "C" void kernel_launch(void* const* d_in, const int* in_sizes, int n_in,
                              void* d_out, int out_size) {
    const float* x     = (const float*)d_in[0];
    const float* w_qkv = (const float*)d_in[1];
    const float* w_o   = (const float*)d_in[2];
    float* out = (float*)d_out;

    const int M = in_sizes[0] / DMODEL;    // 8192
    const int BH = (M / T_SEQ) * NHEADS;   // 32

    cudaFuncSetAttribute(gemm_mma<0>, cudaFuncAttributeMaxDynamicSharedMemorySize, GEMM_SMEM);
    cudaFuncSetAttribute(gemm_mma<1>, cudaFuncAttributeMaxDynamicSharedMemorySize, GEMM_SMEM);
    cudaFuncSetAttribute(attn_chunk_kernel, cudaFuncAttributeMaxDynamicSharedMemorySize,
                         ATTN_SMEM_FLOATS * (int)sizeof(float));

    reset_cnt_kernel<<<1, 32>>>();
    split_kernel<<<(M * DMODEL) / 1024, 256>>>(x, M * DMODEL, 0);
    split_kernel<<<(3 * DMODEL * DMODEL) / 1024, 256>>>(w_qkv, 3 * DMODEL * DMODEL, 1);
    split_kernel<<<(DMODEL * DMODEL) / 1024, 256>>>(w_o, DMODEL * DMODEL, 2);

    dim3 g1(3 * DMODEL / 128, M / 128);
    gemm_mma<0><<<g1, 256, GEMM_SMEM>>>(nullptr);

    fixup_kernel<<<256, 256>>>(x, w_qkv);

    chunk_kv_kernel<<<BH * NCHUNK, 256>>>();
    prefix_kernel<<<BH, 256>>>(out + (size_t)M * DMODEL);
    attn_chunk_kernel<<<BH * NCHUNK, 256, ATTN_SMEM_FLOATS * (int)sizeof(float)>>>();

    dim3 g2(DMODEL / 128, M / 128);
    gemm_mma<1><<<g2, 256, GEMM_SMEM>>>(out);
}

// round 12
// speedup vs baseline: 1.3127x; 1.0042x over previous
#include <cuda_runtime.h>
#include <cuda_fp16.h>
#include <cstdint>

// Problem constants (fixed shapes per reference)
#define T_SEQ   4096
#define DMODEL  1024
#define NHEADS  16
#define DHEAD   64
#define CHUNK   64
#define NCHUNK  (T_SEQ / CHUNK)        // 64
#define QK_SCALE 0.125f                // 1/sqrt(64)
#define BATCH   2
#define MROWS   (BATCH * T_SEQ)        // 8192
#define FIX_TH  3e-3f
#define FIX_CAP (1 << 18)

// fp32 scratch
#define BHTD (BATCH * NHEADS * T_SEQ * DHEAD)
__device__ float g_Q[BHTD];
__device__ float g_K[BHTD];
__device__ float g_V[BHTD];
__device__ float g_CKV[BHTD];

// fp16 split scratch (h = fp16(x), m = fp16(x - h))
__device__ __half g_Xh[MROWS * DMODEL];
__device__ __half g_Xm[MROWS * DMODEL];
__device__ __half g_Wqh[3 * DMODEL * DMODEL];
__device__ __half g_Wqm[3 * DMODEL * DMODEL];
__device__ __half g_Woh[DMODEL * DMODEL];
__device__ __half g_Wom[DMODEL * DMODEL];
__device__ __half g_Oh[BHTD];
__device__ __half g_Om[BHTD];

// near-zero K/V fixup list
__device__ int g_fix_cnt;
__device__ int g_fix_idx[FIX_CAP];

// ---------------------------------------------------------------------------
// helpers
// ---------------------------------------------------------------------------
__device__ __forceinline__ uint32_t smem_u32(const void* p) {
    uint32_t a;
    asm("{ .reg .u64 t; cvta.to.shared.u64 t, %1; cvt.u32.u64 %0, t; }" : "=r"(a) : "l"(p));
    return a;
}
__device__ __forceinline__ void cp16(uint32_t dst, const void* src) {
    asm volatile("cp.async.cg.shared.global [%0], [%1], 16;" :: "r"(dst), "l"(src));
}
__device__ __forceinline__ void cp_commit() {
    asm volatile("cp.async.commit_group;");
}
__device__ __forceinline__ void cp_wait1() {
    asm volatile("cp.async.wait_group 1;" ::: "memory");
}
__device__ __forceinline__ void cp_wait0() {
    asm volatile("cp.async.wait_group 0;" ::: "memory");
}
__device__ __forceinline__ void ldmat4(uint32_t* r, uint32_t addr) {
    asm volatile("ldmatrix.sync.aligned.m8n8.x4.shared.b16 {%0,%1,%2,%3}, [%4];"
                 : "=r"(r[0]), "=r"(r[1]), "=r"(r[2]), "=r"(r[3]) : "r"(addr));
}
__device__ __forceinline__ void mma16816(float* c, const uint32_t* a, uint32_t b0, uint32_t b1) {
    asm volatile(
        "mma.sync.aligned.m16n8k16.row.col.f32.f16.f16.f32 "
        "{%0,%1,%2,%3}, {%4,%5,%6,%7}, {%8,%9}, {%0,%1,%2,%3};"
        : "+f"(c[0]), "+f"(c[1]), "+f"(c[2]), "+f"(c[3])
        : "r"(a[0]), "r"(a[1]), "r"(a[2]), "r"(a[3]), "r"(b0), "r"(b1));
}

// ---------------------------------------------------------------------------
// Split fp32 -> (h, m) fp16.  sel: 0=x, 1=w_qkv, 2=w_o
// ---------------------------------------------------------------------------
__global__ __launch_bounds__(256) void split_kernel(const float* __restrict__ src,
                                                    int n, int sel) {
    __half *hp, *mp;
    if (sel == 0)      { hp = g_Xh;  mp = g_Xm;  }
    else if (sel == 1) { hp = g_Wqh; mp = g_Wqm; }
    else               { hp = g_Woh; mp = g_Wom; }
    int i = (blockIdx.x * 256 + threadIdx.x) * 4;
    if (i >= n) return;
    float4 v = *(const float4*)(src + i);
    float xs[4] = {v.x, v.y, v.z, v.w};
    __align__(8) __half hb[4], mb[4];
#pragma unroll
    for (int j = 0; j < 4; j++) {
        __half h = __float2half_rn(xs[j]);
        float r = xs[j] - __half2float(h);
        hb[j] = h; mb[j] = __float2half_rn(r);
    }
    *(uint2*)(hp + i) = *(uint2*)hb;
    *(uint2*)(mp + i) = *(uint2*)mb;
}

__global__ void reset_cnt_kernel() { if (threadIdx.x == 0) g_fix_cnt = 0; }

// ---------------------------------------------------------------------------
// Split-fp16 HMMA GEMM. CTA tile 128x128, 8 warps (warp tile 64x32), K-chunks
// of 64 (halved barrier/issue overhead vs 32), double-buffered cp.async.
// MODE 0: QKV = X @ Wqkv^T.
//         Q tiles (bn<1024): 3 products (AhBh, AhBm, AmBh) -> scale, store.
//         K/V tiles:         1 product  (AhBh) -> binarize + near-zero flags
//                            (only Ah and Bh tiles loaded).
// MODE 1: out = O(gathered) @ Wo^T, 3 products, plain store.
// ---------------------------------------------------------------------------
#define KC      64                           // k-chunk (elements)
#define LDP     72                           // padded row pitch (elements)
#define TILE_E  (128 * LDP)                  // elements per tile (9216)
#define TILE_B2 (TILE_E * 2)                 // bytes per tile (18432)
#define STAGE_B (4 * TILE_B2)                // Ah, Am, Bh, Bm (73728 B)
#define GEMM_SMEM (2 * STAGE_B)              // 147456 bytes

template<int MODE>
__global__ __launch_bounds__(256) void gemm_mma(float* __restrict__ outp) {
    extern __shared__ __align__(128) char smc[];
    const uint32_t smb = smem_u32(smc);
    const int tid = threadIdx.x;
    const int wid = tid >> 5;
    const int lane = tid & 31;
    const int bn = blockIdx.x * 128;
    const int bm = blockIdx.y * 128;
    const int wm = wid & 1;      // 2 m-blocks of 64
    const int wn = wid >> 1;     // 4 n-blocks of 32
    const int nprod = (MODE == 0) ? ((bn >= 1024) ? 1 : 3) : 3;
    const bool needM = (nprod == 3);     // Am/Bm tiles needed?

    // gmem source bases
    const __half *Ah, *Am, *Bh, *Bm;
    int bb = 0, tbase = 0;
    if (MODE == 0) {
        Ah = g_Xh + (size_t)bm * DMODEL;  Am = g_Xm + (size_t)bm * DMODEL;
        Bh = g_Wqh + (size_t)bn * DMODEL; Bm = g_Wqm + (size_t)bn * DMODEL;
    } else {
        bb = bm >> 12; tbase = bm & (T_SEQ - 1);
        Ah = g_Oh; Am = g_Om;
        Bh = g_Woh + (size_t)bn * DMODEL; Bm = g_Wom + (size_t)bn * DMODEL;
    }

    // per-thread gmem->smem slots: 128 rows x 8 quads = 1024 slots, 4/thread
    auto load_stage = [&](int c, int st) {
        const int k0 = c * KC;
        const uint32_t stg = smb + (uint32_t)st * STAGE_B;
#pragma unroll
        for (int t = 0; t < 4; t++) {
            if ((t == 1 || t == 3) && !needM) continue;  // KV tiles: only h
            const __half* base;
            size_t roff; int rstride;
            if (MODE == 0 || t >= 2) {
                base = (t == 0) ? Ah : (t == 1) ? Am : (t == 2) ? Bh : Bm;
                roff = (size_t)k0; rstride = DMODEL;
            } else {
                // gemm1 A gather: chunk c == head c, rows contiguous 64-wide
                base = (t == 0) ? Ah : Am;
                int bh = bb * NHEADS + c;
                roff = ((size_t)bh * T_SEQ + tbase) * DHEAD;
                rstride = DHEAD;
            }
            const uint32_t tb = stg + (uint32_t)t * TILE_B2;
#pragma unroll
            for (int i = 0; i < 4; i++) {
                int slot = tid + i * 256;
                int row = slot >> 3, quad = slot & 7;
                cp16(tb + (uint32_t)(row * LDP + quad * 8) * 2,
                     base + roff + (size_t)row * rstride + quad * 8);
            }
        }
        cp_commit();
    };

    // ldmatrix lane address bases (relative element offsets within a tile)
    const int a_base = (wm * 64 + (lane & 15)) * LDP + (lane >> 4) * 8;
    const int b_base = (wn * 32 + (lane & 7) + (lane >> 4) * 8) * LDP + ((lane >> 3) & 1) * 8;

    float acc[4][4][4];
#pragma unroll
    for (int i = 0; i < 4; i++)
#pragma unroll
        for (int j = 0; j < 4; j++)
#pragma unroll
            for (int r = 0; r < 4; r++) acc[i][j][r] = 0.f;

    const int prodA[3] = {0, 0, 1};   // Ah, Ah, Am
    const int prodB[3] = {2, 3, 2};   // Bh, Bm, Bh

    load_stage(0, 0);
    const int NCH = DMODEL / KC;      // 16
    for (int c = 0; c < NCH; c++) {
        if (c + 1 < NCH) { load_stage(c + 1, (c + 1) & 1); cp_wait1(); }
        else cp_wait0();
        __syncthreads();
        const uint32_t stg = smb + (uint32_t)(c & 1) * STAGE_B;
        for (int p = 0; p < nprod; p++) {
            const uint32_t At = stg + (uint32_t)prodA[p] * TILE_B2;
            const uint32_t Bt = stg + (uint32_t)prodB[p] * TILE_B2;
#pragma unroll
            for (int s = 0; s < 4; s++) {
                uint32_t a[4][4], b[2][4];
#pragma unroll
                for (int mi = 0; mi < 4; mi++)
                    ldmat4(a[mi], At + (uint32_t)(a_base + mi * 16 * LDP + s * 16) * 2);
#pragma unroll
                for (int ni2 = 0; ni2 < 2; ni2++)
                    ldmat4(b[ni2], Bt + (uint32_t)(b_base + ni2 * 16 * LDP + s * 16) * 2);
#pragma unroll
                for (int mi = 0; mi < 4; mi++)
#pragma unroll
                    for (int ni = 0; ni < 4; ni++)
                        mma16816(acc[mi][ni], a[mi], b[ni >> 1][(ni & 1) * 2],
                                 b[ni >> 1][(ni & 1) * 2 + 1]);
            }
        }
        __syncthreads();
    }

    // epilogue: D frag (m16n8): c0,c1 row=lane>>2, cols 2*(lane&3)+{0,1}; c2,c3 row+8
    const int r0l = lane >> 2;
    const int cbl = (lane & 3) * 2;
#pragma unroll
    for (int mi = 0; mi < 4; mi++) {
#pragma unroll
        for (int ni = 0; ni < 4; ni++) {
#pragma unroll
            for (int half = 0; half < 2; half++) {
                int row = bm + wm * 64 + mi * 16 + r0l + half * 8;
                int col = bn + wn * 32 + ni * 8 + cbl;
                float v0 = acc[mi][ni][half * 2];
                float v1 = acc[mi][ni][half * 2 + 1];
                if (MODE == 0) {
                    int mb = row >> 12, t = row & (T_SEQ - 1);
                    int which = col >> 10, h = (col >> 6) & 15, l = col & 63;
                    size_t dst = (((size_t)(mb * NHEADS + h)) * T_SEQ + t) * DHEAD + l;
                    if (which == 0) {
                        float2 o; o.x = v0 * QK_SCALE; o.y = v1 * QK_SCALE;
                        *(float2*)(g_Q + dst) = o;
                    } else {
                        float* base = (which == 1) ? g_K : g_V;
                        float2 o;
                        o.x = (v0 >= 0.f) ? 1.f : -1.f;
                        o.y = (v1 >= 0.f) ? 1.f : -1.f;
                        *(float2*)(base + dst) = o;
                        if (fabsf(v0) < FIX_TH) {
                            int idx = atomicAdd(&g_fix_cnt, 1);
                            if (idx < FIX_CAP) g_fix_idx[idx] = row * 3072 + col;
                        }
                        if (fabsf(v1) < FIX_TH) {
                            int idx = atomicAdd(&g_fix_cnt, 1);
                            if (idx < FIX_CAP) g_fix_idx[idx] = row * 3072 + col + 1;
                        }
                    }
                } else {
                    float2 o; o.x = v0; o.y = v1;
                    *(float2*)(outp + (size_t)row * DMODEL + col) = o;
                }
            }
        }
    }
}

// ---------------------------------------------------------------------------
// Exact fp32 recompute of flagged near-zero K/V elements. One thread per
// element, STRICTLY SEQUENTIAL k-order FMA chain (matches the summation order
// that empirically reproduced the reference's signs in rounds 1 and 6-11).
// ---------------------------------------------------------------------------
__global__ __launch_bounds__(256) void fixup_kernel(const float* __restrict__ x,
                                                    const float* __restrict__ w) {
    int cnt = g_fix_cnt; if (cnt > FIX_CAP) cnt = FIX_CAP;
    const int stride = gridDim.x * blockDim.x;
    for (int i = blockIdx.x * blockDim.x + threadIdx.x; i < cnt; i += stride) {
        int code = g_fix_idx[i];
        int m = code / 3072, n = code % 3072;
        const float4* xr = (const float4*)(x + (size_t)m * DMODEL);
        const float4* wr = (const float4*)(w + (size_t)n * DMODEL);
        float acc = 0.f;
#pragma unroll 4
        for (int j = 0; j < DMODEL / 4; j++) {
            float4 a = xr[j], b = wr[j];
            acc = fmaf(a.x, b.x, acc);
            acc = fmaf(a.y, b.y, acc);
            acc = fmaf(a.z, b.z, acc);
            acc = fmaf(a.w, b.w, acc);
        }
        int mb = m >> 12, t = m & (T_SEQ - 1);
        int h = (n >> 6) & 15, l = n & 63;
        float* base = ((n >> 10) == 1) ? g_K : g_V;
        base[(((size_t)(mb * NHEADS + h)) * T_SEQ + t) * DHEAD + l] = (acc >= 0.f) ? 1.f : -1.f;
    }
}

// ---------------------------------------------------------------------------
// chunk_kv[bh][n][k][v] = sum_t kc[t][k] * vc[t][v]
// ---------------------------------------------------------------------------
__global__ __launch_bounds__(256) void chunk_kv_kernel() {
    __shared__ float ks[CHUNK * DHEAD];
    __shared__ float vs[CHUNK * DHEAD];
    const int tid = threadIdx.x;
    const int n = blockIdx.x & (NCHUNK - 1);
    const int bh = blockIdx.x >> 6;
    const float* kg = g_K + ((size_t)bh * T_SEQ + n * CHUNK) * DHEAD;
    const float* vg = g_V + ((size_t)bh * T_SEQ + n * CHUNK) * DHEAD;
    for (int f = tid; f < 1024; f += 256) {
        ((float4*)ks)[f] = ((const float4*)kg)[f];
        ((float4*)vs)[f] = ((const float4*)vg)[f];
    }
    __syncthreads();
    const int kk0 = (tid >> 4) * 4;
    const int vv0 = (tid & 15) * 4;
    float acc[4][4] = {};
#pragma unroll 4
    for (int t = 0; t < CHUNK; t++) {
        float kv[4];
        *(float4*)kv = *(const float4*)&ks[t * DHEAD + kk0];
        float4 v4 = *(const float4*)&vs[t * DHEAD + vv0];
#pragma unroll
        for (int ii = 0; ii < 4; ii++) {
            acc[ii][0] += kv[ii] * v4.x;
            acc[ii][1] += kv[ii] * v4.y;
            acc[ii][2] += kv[ii] * v4.z;
            acc[ii][3] += kv[ii] * v4.w;
        }
    }
    float* cg = g_CKV + ((size_t)bh * NCHUNK + n) * (DHEAD * DHEAD);
#pragma unroll
    for (int ii = 0; ii < 4; ii++) {
        float4 o; o.x = acc[ii][0]; o.y = acc[ii][1]; o.z = acc[ii][2]; o.w = acc[ii][3];
        *(float4*)&cg[(kk0 + ii) * DHEAD + vv0] = o;
    }
}

// ---------------------------------------------------------------------------
// In-place exclusive prefix over chunks; writes final_state. (R5 simple form)
// ---------------------------------------------------------------------------
__global__ __launch_bounds__(256) void prefix_kernel(float* __restrict__ final_out) {
    const int tid = threadIdx.x;
    const int bh = blockIdx.x;
    float run[16];
#pragma unroll
    for (int j = 0; j < 16; j++) run[j] = 0.f;
    for (int n = 0; n < NCHUNK; n++) {
        float* p = g_CKV + ((size_t)bh * NCHUNK + n) * (DHEAD * DHEAD) + tid * 16;
        float tmp[16];
#pragma unroll
        for (int q = 0; q < 4; q++) ((float4*)tmp)[q] = ((float4*)p)[q];
#pragma unroll
        for (int q = 0; q < 4; q++) ((float4*)p)[q] = ((float4*)run)[q];
#pragma unroll
        for (int j = 0; j < 16; j++) run[j] += tmp[j];
    }
    float* fo = final_out + (size_t)bh * (DHEAD * DHEAD) + tid * 16;
#pragma unroll
    for (int q = 0; q < 4; q++) ((float4*)fo)[q] = ((float4*)run)[q];
}

// ---------------------------------------------------------------------------
// Per-chunk attention: out = tril(q@k^T)@v + q@prefix
// Epilogue writes the fp16 (h,m) split of the output directly (fused split).
// ---------------------------------------------------------------------------
#define KT_PITCH 68
#define ATTN_SMEM_FLOATS (4096 + CHUNK * KT_PITCH + 4096 + 4096)

__global__ __launch_bounds__(256) void attn_chunk_kernel() {
    extern __shared__ float smf[];
    float* qs = smf;
    float* kp = smf + 4096;
    float* vs = kp + CHUNK * KT_PITCH;
    float* ss = vs + 4096;

    const int tid = threadIdx.x;
    const int n = blockIdx.x & (NCHUNK - 1);
    const int bh = blockIdx.x >> 6;

    const float* qg = g_Q + ((size_t)bh * T_SEQ + n * CHUNK) * DHEAD;
    const float* kg = g_K + ((size_t)bh * T_SEQ + n * CHUNK) * DHEAD;
    const float* vg = g_V + ((size_t)bh * T_SEQ + n * CHUNK) * DHEAD;

    for (int f = tid; f < 1024; f += 256) {
        ((float4*)qs)[f] = ((const float4*)qg)[f];
        ((float4*)vs)[f] = ((const float4*)vg)[f];
        int j = f >> 4;
        int lq = (f & 15) << 2;
        float4 kv = ((const float4*)kg)[f];
        kp[(lq + 0) * KT_PITCH + j] = kv.x;
        kp[(lq + 1) * KT_PITCH + j] = kv.y;
        kp[(lq + 2) * KT_PITCH + j] = kv.z;
        kp[(lq + 3) * KT_PITCH + j] = kv.w;
    }
    __syncthreads();

    const int i0 = (tid >> 4) * 4;
    const int c0 = (tid & 15) * 4;

    {
        float sa[4][4] = {};
#pragma unroll 4
        for (int l = 0; l < DHEAD; l++) {
            float q4[4];
#pragma unroll
            for (int ii = 0; ii < 4; ii++) q4[ii] = qs[(i0 + ii) * DHEAD + l];
            float4 k4 = *(const float4*)&kp[l * KT_PITCH + c0];
#pragma unroll
            for (int ii = 0; ii < 4; ii++) {
                sa[ii][0] += q4[ii] * k4.x;
                sa[ii][1] += q4[ii] * k4.y;
                sa[ii][2] += q4[ii] * k4.z;
                sa[ii][3] += q4[ii] * k4.w;
            }
        }
#pragma unroll
        for (int ii = 0; ii < 4; ii++) {
            int i = i0 + ii;
#pragma unroll
            for (int jj = 0; jj < 4; jj++) {
                int j = c0 + jj;
                ss[i * CHUNK + j] = (j <= i) ? sa[ii][jj] : 0.f;
            }
        }
    }
    __syncthreads();

    {
        const float* pg = g_CKV + ((size_t)bh * NCHUNK + n) * (DHEAD * DHEAD);
        for (int f = tid; f < 1024; f += 256) ((float4*)kp)[f] = ((const float4*)pg)[f];
    }
    __syncthreads();

    {
        float oa[4][4] = {};
#pragma unroll 4
        for (int j = 0; j < CHUNK; j++) {
            float s4[4];
#pragma unroll
            for (int ii = 0; ii < 4; ii++) s4[ii] = ss[(i0 + ii) * CHUNK + j];
            float4 v4 = *(const float4*)&vs[j * DHEAD + c0];
#pragma unroll
            for (int ii = 0; ii < 4; ii++) {
                oa[ii][0] += s4[ii] * v4.x;
                oa[ii][1] += s4[ii] * v4.y;
                oa[ii][2] += s4[ii] * v4.z;
                oa[ii][3] += s4[ii] * v4.w;
            }
        }
#pragma unroll 4
        for (int k = 0; k < DHEAD; k++) {
            float q4[4];
#pragma unroll
            for (int ii = 0; ii < 4; ii++) q4[ii] = qs[(i0 + ii) * DHEAD + k];
            float4 p4 = *(const float4*)&kp[k * DHEAD + c0];
#pragma unroll
            for (int ii = 0; ii < 4; ii++) {
                oa[ii][0] += q4[ii] * p4.x;
                oa[ii][1] += q4[ii] * p4.y;
                oa[ii][2] += q4[ii] * p4.z;
                oa[ii][3] += q4[ii] * p4.w;
            }
        }
        // fused fp16 (h, m) split store
        __half* ohg = g_Oh + ((size_t)bh * T_SEQ + n * CHUNK) * DHEAD;
        __half* omg = g_Om + ((size_t)bh * T_SEQ + n * CHUNK) * DHEAD;
#pragma unroll
        for (int ii = 0; ii < 4; ii++) {
            __align__(8) __half hb[4], mb[4];
#pragma unroll
            for (int jj = 0; jj < 4; jj++) {
                float v = oa[ii][jj];
                __half h = __float2half_rn(v);
                hb[jj] = h;
                mb[jj] = __float2half_rn(v - __half2float(h));
            }
            *(uint2*)(ohg + (i0 + ii) * DHEAD + c0) = *(uint2*)hb;
            *(uint2*)(omg + (i0 + ii) * DHEAD + c0) = *(uint2*)mb;
        }
    }
}

// ---------------------------------------------------------------------------
extern "C" void kernel_launch(void* const* d_in, const int* in_sizes, int n_in,
                              void* d_out, int out_size) {
    const float* x     = (const float*)d_in[0];
    const float* w_qkv = (const float*)d_in[1];
    const float* w_o   = (const float*)d_in[2];
    float* out = (float*)d_out;

    const int M = in_sizes[0] / DMODEL;    // 8192
    const int BH = (M / T_SEQ) * NHEADS;   // 32

    cudaFuncSetAttribute(gemm_mma<0>, cudaFuncAttributeMaxDynamicSharedMemorySize, GEMM_SMEM);
    cudaFuncSetAttribute(gemm_mma<1>, cudaFuncAttributeMaxDynamicSharedMemorySize, GEMM_SMEM);
    cudaFuncSetAttribute(attn_chunk_kernel, cudaFuncAttributeMaxDynamicSharedMemorySize,
                         ATTN_SMEM_FLOATS * (int)sizeof(float));

    reset_cnt_kernel<<<1, 32>>>();
    split_kernel<<<(M * DMODEL) / 1024, 256>>>(x, M * DMODEL, 0);
    split_kernel<<<(3 * DMODEL * DMODEL) / 1024, 256>>>(w_qkv, 3 * DMODEL * DMODEL, 1);
    split_kernel<<<(DMODEL * DMODEL) / 1024, 256>>>(w_o, DMODEL * DMODEL, 2);

    dim3 g1(3 * DMODEL / 128, M / 128);
    gemm_mma<0><<<g1, 256, GEMM_SMEM>>>(nullptr);

    fixup_kernel<<<256, 256>>>(x, w_qkv);

    chunk_kv_kernel<<<BH * NCHUNK, 256>>>();
    prefix_kernel<<<BH, 256>>>(out + (size_t)M * DMODEL);
    attn_chunk_kernel<<<BH * NCHUNK, 256, ATTN_SMEM_FLOATS * (int)sizeof(float)>>>();

    dim3 g2(DMODEL / 128, M / 128);
    gemm_mma<1><<<g2, 256, GEMM_SMEM>>>(out);
}

// round 14
// speedup vs baseline: 1.6297x; 1.2415x over previous
#include <cuda_runtime.h>
#include <cuda_fp16.h>
#include <cstdint>

// Problem constants (fixed shapes per reference)
#define T_SEQ   4096
#define DMODEL  1024
#define NHEADS  16
#define DHEAD   64
#define CHUNK   64
#define NCHUNK  (T_SEQ / CHUNK)        // 64
#define QK_SCALE 0.125f                // 1/sqrt(64)
#define BATCH   2
#define MROWS   (BATCH * T_SEQ)        // 8192
#define FIX_TH  3e-3f
#define FIX_CAP (1 << 18)

// fp32 scratch
#define BHTD (BATCH * NHEADS * T_SEQ * DHEAD)
__device__ float g_Q[BHTD];
__device__ float g_K[BHTD];
__device__ float g_V[BHTD];
__device__ float g_CKV[BHTD];

// fp16 split scratch (h = fp16(x), m = fp16(x - h))
__device__ __half g_Xh[MROWS * DMODEL];
__device__ __half g_Wqh[3 * DMODEL * DMODEL];
__device__ __half g_Wqm[3 * DMODEL * DMODEL];
__device__ __half g_Woh[DMODEL * DMODEL];
__device__ __half g_Wom[DMODEL * DMODEL];
__device__ __half g_Oh[BHTD];

// near-zero K/V fixup list
__device__ int g_fix_cnt;
__device__ int g_fix_idx[FIX_CAP];

// ---------------------------------------------------------------------------
// helpers
// ---------------------------------------------------------------------------
__device__ __forceinline__ uint32_t smem_u32(const void* p) {
    uint32_t a;
    asm("{ .reg .u64 t; cvta.to.shared.u64 t, %1; cvt.u32.u64 %0, t; }" : "=r"(a) : "l"(p));
    return a;
}
__device__ __forceinline__ void cp16(uint32_t dst, const void* src) {
    asm volatile("cp.async.cg.shared.global [%0], [%1], 16;" :: "r"(dst), "l"(src));
}
__device__ __forceinline__ void cp_commit() {
    asm volatile("cp.async.commit_group;");
}
__device__ __forceinline__ void cp_wait1() {
    asm volatile("cp.async.wait_group 1;" ::: "memory");
}
__device__ __forceinline__ void cp_wait0() {
    asm volatile("cp.async.wait_group 0;" ::: "memory");
}
__device__ __forceinline__ void ldmat4(uint32_t* r, uint32_t addr) {
    asm volatile("ldmatrix.sync.aligned.m8n8.x4.shared.b16 {%0,%1,%2,%3}, [%4];"
                 : "=r"(r[0]), "=r"(r[1]), "=r"(r[2]), "=r"(r[3]) : "r"(addr));
}
__device__ __forceinline__ void mma16816(float* c, const uint32_t* a, uint32_t b0, uint32_t b1) {
    asm volatile(
        "mma.sync.aligned.m16n8k16.row.col.f32.f16.f16.f32 "
        "{%0,%1,%2,%3}, {%4,%5,%6,%7}, {%8,%9}, {%0,%1,%2,%3};"
        : "+f"(c[0]), "+f"(c[1]), "+f"(c[2]), "+f"(c[3])
        : "r"(a[0]), "r"(a[1]), "r"(a[2]), "r"(a[3]), "r"(b0), "r"(b1));
}

// ---------------------------------------------------------------------------
// Split fp32 -> fp16 (h, and m for weights).  sel: 0=x (h only), 1=w_qkv, 2=w_o
// ---------------------------------------------------------------------------
__global__ __launch_bounds__(256) void split_kernel(const float* __restrict__ src,
                                                    int n, int sel) {
    __half *hp, *mp = nullptr;
    if (sel == 0)      { hp = g_Xh; }
    else if (sel == 1) { hp = g_Wqh; mp = g_Wqm; }
    else               { hp = g_Woh; mp = g_Wom; }
    int i = (blockIdx.x * 256 + threadIdx.x) * 4;
    if (i >= n) return;
    float4 v = *(const float4*)(src + i);
    float xs[4] = {v.x, v.y, v.z, v.w};
    __align__(8) __half hb[4], mb[4];
#pragma unroll
    for (int j = 0; j < 4; j++) {
        __half h = __float2half_rn(xs[j]);
        float r = xs[j] - __half2float(h);
        hb[j] = h; mb[j] = __float2half_rn(r);
    }
    *(uint2*)(hp + i) = *(uint2*)hb;
    if (mp) *(uint2*)(mp + i) = *(uint2*)mb;
}

__global__ void reset_cnt_kernel() { if (threadIdx.x == 0) g_fix_cnt = 0; }

// ---------------------------------------------------------------------------
// Split-fp16 HMMA GEMM. CTA tile 128x128, 8 warps (warp tile 64x32), K-chunks
// of 64, double-buffered cp.async. A-residual products eliminated: only Ah
// is ever loaded. Stage holds 3 tiles: A(0), Bh(1), Bm(2).
// MODE 0: QKV = X @ Wqkv^T.
//         Q tiles (bn<1024): 2 products (AhBh, AhBm) -> scale, store.
//         K/V tiles:         1 product  (AhBh) -> binarize + near-zero flags.
// MODE 1: out = Oh(gathered) @ Wo^T, 2 products (AhBh, AhBm), plain store.
// ---------------------------------------------------------------------------
#define KC      64                           // k-chunk (elements)
#define LDP     72                           // padded row pitch (elements)
#define TILE_E  (128 * LDP)                  // elements per tile (9216)
#define TILE_B2 (TILE_E * 2)                 // bytes per tile (18432)
#define STAGE_B (3 * TILE_B2)                // A, Bh, Bm (55296 B)
#define GEMM_SMEM (2 * STAGE_B)              // 110592 bytes

template<int MODE>
__global__ __launch_bounds__(256) void gemm_mma(float* __restrict__ outp) {
    extern __shared__ __align__(128) char smc[];
    const uint32_t smb = smem_u32(smc);
    const int tid = threadIdx.x;
    const int wid = tid >> 5;
    const int lane = tid & 31;
    const int bn = blockIdx.x * 128;
    const int bm = blockIdx.y * 128;
    const int wm = wid & 1;      // 2 m-blocks of 64
    const int wn = wid >> 1;     // 4 n-blocks of 32
    const int nprod = (MODE == 0) ? ((bn >= 1024) ? 1 : 2) : 2;

    // gmem source bases
    const __half *Ah, *Bh, *Bm;
    int bb = 0, tbase = 0;
    if (MODE == 0) {
        Ah = g_Xh + (size_t)bm * DMODEL;
        Bh = g_Wqh + (size_t)bn * DMODEL; Bm = g_Wqm + (size_t)bn * DMODEL;
    } else {
        bb = bm >> 12; tbase = bm & (T_SEQ - 1);
        Ah = g_Oh;
        Bh = g_Woh + (size_t)bn * DMODEL; Bm = g_Wom + (size_t)bn * DMODEL;
    }

    // per-thread gmem->smem slots: 128 rows x 8 quads = 1024 slots, 4/thread
    auto load_stage = [&](int c, int st) {
        const int k0 = c * KC;
        const uint32_t stg = smb + (uint32_t)st * STAGE_B;
#pragma unroll
        for (int t = 0; t < 3; t++) {
            if (t == 2 && nprod == 1) continue;          // KV tiles: no Bm
            const __half* base;
            size_t roff; int rstride;
            if (MODE == 0 || t >= 1) {
                base = (t == 0) ? Ah : (t == 1) ? Bh : Bm;
                roff = (size_t)k0; rstride = DMODEL;
            } else {
                // gemm1 A gather: chunk c == head c, rows contiguous 64-wide
                base = Ah;
                int bh = bb * NHEADS + c;
                roff = ((size_t)bh * T_SEQ + tbase) * DHEAD;
                rstride = DHEAD;
            }
            const uint32_t tb = stg + (uint32_t)t * TILE_B2;
#pragma unroll
            for (int i = 0; i < 4; i++) {
                int slot = tid + i * 256;
                int row = slot >> 3, quad = slot & 7;
                cp16(tb + (uint32_t)(row * LDP + quad * 8) * 2,
                     base + roff + (size_t)row * rstride + quad * 8);
            }
        }
        cp_commit();
    };

    // ldmatrix lane address bases (relative element offsets within a tile)
    const int a_base = (wm * 64 + (lane & 15)) * LDP + (lane >> 4) * 8;
    const int b_base = (wn * 32 + (lane & 7) + (lane >> 4) * 8) * LDP + ((lane >> 3) & 1) * 8;

    float acc[4][4][4];
#pragma unroll
    for (int i = 0; i < 4; i++)
#pragma unroll
        for (int j = 0; j < 4; j++)
#pragma unroll
            for (int r = 0; r < 4; r++) acc[i][j][r] = 0.f;

    load_stage(0, 0);
    const int NCH = DMODEL / KC;      // 16
    for (int c = 0; c < NCH; c++) {
        if (c + 1 < NCH) { load_stage(c + 1, (c + 1) & 1); cp_wait1(); }
        else cp_wait0();
        __syncthreads();
        const uint32_t stg = smb + (uint32_t)(c & 1) * STAGE_B;
        for (int p = 0; p < nprod; p++) {
            const uint32_t At = stg;                                   // A slot 0
            const uint32_t Bt = stg + (uint32_t)(1 + p) * TILE_B2;     // Bh or Bm
#pragma unroll
            for (int s = 0; s < 4; s++) {
                uint32_t a[4][4], b[2][4];
#pragma unroll
                for (int mi = 0; mi < 4; mi++)
                    ldmat4(a[mi], At + (uint32_t)(a_base + mi * 16 * LDP + s * 16) * 2);
#pragma unroll
                for (int ni2 = 0; ni2 < 2; ni2++)
                    ldmat4(b[ni2], Bt + (uint32_t)(b_base + ni2 * 16 * LDP + s * 16) * 2);
#pragma unroll
                for (int mi = 0; mi < 4; mi++)
#pragma unroll
                    for (int ni = 0; ni < 4; ni++)
                        mma16816(acc[mi][ni], a[mi], b[ni >> 1][(ni & 1) * 2],
                                 b[ni >> 1][(ni & 1) * 2 + 1]);
            }
        }
        __syncthreads();
    }

    // epilogue: D frag (m16n8): c0,c1 row=lane>>2, cols 2*(lane&3)+{0,1}; c2,c3 row+8
    const int r0l = lane >> 2;
    const int cbl = (lane & 3) * 2;
#pragma unroll
    for (int mi = 0; mi < 4; mi++) {
#pragma unroll
        for (int ni = 0; ni < 4; ni++) {
#pragma unroll
            for (int half = 0; half < 2; half++) {
                int row = bm + wm * 64 + mi * 16 + r0l + half * 8;
                int col = bn + wn * 32 + ni * 8 + cbl;
                float v0 = acc[mi][ni][half * 2];
                float v1 = acc[mi][ni][half * 2 + 1];
                if (MODE == 0) {
                    int mb = row >> 12, t = row & (T_SEQ - 1);
                    int which = col >> 10, h = (col >> 6) & 15, l = col & 63;
                    size_t dst = (((size_t)(mb * NHEADS + h)) * T_SEQ + t) * DHEAD + l;
                    if (which == 0) {
                        float2 o; o.x = v0 * QK_SCALE; o.y = v1 * QK_SCALE;
                        *(float2*)(g_Q + dst) = o;
                    } else {
                        float* base = (which == 1) ? g_K : g_V;
                        float2 o;
                        o.x = (v0 >= 0.f) ? 1.f : -1.f;
                        o.y = (v1 >= 0.f) ? 1.f : -1.f;
                        *(float2*)(base + dst) = o;
                        if (fabsf(v0) < FIX_TH) {
                            int idx = atomicAdd(&g_fix_cnt, 1);
                            if (idx < FIX_CAP) g_fix_idx[idx] = row * 3072 + col;
                        }
                        if (fabsf(v1) < FIX_TH) {
                            int idx = atomicAdd(&g_fix_cnt, 1);
                            if (idx < FIX_CAP) g_fix_idx[idx] = row * 3072 + col + 1;
                        }
                    }
                } else {
                    float2 o; o.x = v0; o.y = v1;
                    *(float2*)(outp + (size_t)row * DMODEL + col) = o;
                }
            }
        }
    }
}

// ---------------------------------------------------------------------------
// Exact fp32 recompute of flagged near-zero K/V elements. One thread per
// element, STRICTLY SEQUENTIAL k-order FMA chain (matches the summation order
// that empirically reproduced the reference's signs in rounds 1 and 6-12).
// ---------------------------------------------------------------------------
__global__ __launch_bounds__(256) void fixup_kernel(const float* __restrict__ x,
                                                    const float* __restrict__ w) {
    int cnt = g_fix_cnt; if (cnt > FIX_CAP) cnt = FIX_CAP;
    const int stride = gridDim.x * blockDim.x;
    for (int i = blockIdx.x * blockDim.x + threadIdx.x; i < cnt; i += stride) {
        int code = g_fix_idx[i];
        int m = code / 3072, n = code % 3072;
        const float4* xr = (const float4*)(x + (size_t)m * DMODEL);
        const float4* wr = (const float4*)(w + (size_t)n * DMODEL);
        float acc = 0.f;
#pragma unroll 4
        for (int j = 0; j < DMODEL / 4; j++) {
            float4 a = xr[j], b = wr[j];
            acc = fmaf(a.x, b.x, acc);
            acc = fmaf(a.y, b.y, acc);
            acc = fmaf(a.z, b.z, acc);
            acc = fmaf(a.w, b.w, acc);
        }
        int mb = m >> 12, t = m & (T_SEQ - 1);
        int h = (n >> 6) & 15, l = n & 63;
        float* base = ((n >> 10) == 1) ? g_K : g_V;
        base[(((size_t)(mb * NHEADS + h)) * T_SEQ + t) * DHEAD + l] = (acc >= 0.f) ? 1.f : -1.f;
    }
}

// ---------------------------------------------------------------------------
// chunk_kv[bh][n][k][v] = sum_t kc[t][k] * vc[t][v]
// ---------------------------------------------------------------------------
__global__ __launch_bounds__(256) void chunk_kv_kernel() {
    __shared__ float ks[CHUNK * DHEAD];
    __shared__ float vs[CHUNK * DHEAD];
    const int tid = threadIdx.x;
    const int n = blockIdx.x & (NCHUNK - 1);
    const int bh = blockIdx.x >> 6;
    const float* kg = g_K + ((size_t)bh * T_SEQ + n * CHUNK) * DHEAD;
    const float* vg = g_V + ((size_t)bh * T_SEQ + n * CHUNK) * DHEAD;
    for (int f = tid; f < 1024; f += 256) {
        ((float4*)ks)[f] = ((const float4*)kg)[f];
        ((float4*)vs)[f] = ((const float4*)vg)[f];
    }
    __syncthreads();
    const int kk0 = (tid >> 4) * 4;
    const int vv0 = (tid & 15) * 4;
    float acc[4][4] = {};
#pragma unroll 4
    for (int t = 0; t < CHUNK; t++) {
        float kv[4];
        *(float4*)kv = *(const float4*)&ks[t * DHEAD + kk0];
        float4 v4 = *(const float4*)&vs[t * DHEAD + vv0];
#pragma unroll
        for (int ii = 0; ii < 4; ii++) {
            acc[ii][0] += kv[ii] * v4.x;
            acc[ii][1] += kv[ii] * v4.y;
            acc[ii][2] += kv[ii] * v4.z;
            acc[ii][3] += kv[ii] * v4.w;
        }
    }
    float* cg = g_CKV + ((size_t)bh * NCHUNK + n) * (DHEAD * DHEAD);
#pragma unroll
    for (int ii = 0; ii < 4; ii++) {
        float4 o; o.x = acc[ii][0]; o.y = acc[ii][1]; o.z = acc[ii][2]; o.w = acc[ii][3];
        *(float4*)&cg[(kk0 + ii) * DHEAD + vv0] = o;
    }
}

// ---------------------------------------------------------------------------
// In-place exclusive prefix over chunks; writes final_state. (R5 simple form)
// ---------------------------------------------------------------------------
__global__ __launch_bounds__(256) void prefix_kernel(float* __restrict__ final_out) {
    const int tid = threadIdx.x;
    const int bh = blockIdx.x;
    float run[16];
#pragma unroll
    for (int j = 0; j < 16; j++) run[j] = 0.f;
    for (int n = 0; n < NCHUNK; n++) {
        float* p = g_CKV + ((size_t)bh * NCHUNK + n) * (DHEAD * DHEAD) + tid * 16;
        float tmp[16];
#pragma unroll
        for (int q = 0; q < 4; q++) ((float4*)tmp)[q] = ((float4*)p)[q];
#pragma unroll
        for (int q = 0; q < 4; q++) ((float4*)p)[q] = ((float4*)run)[q];
#pragma unroll
        for (int j = 0; j < 16; j++) run[j] += tmp[j];
    }
    float* fo = final_out + (size_t)bh * (DHEAD * DHEAD) + tid * 16;
#pragma unroll
    for (int q = 0; q < 4; q++) ((float4*)fo)[q] = ((float4*)run)[q];
}

// ---------------------------------------------------------------------------
// Per-chunk attention: out = tril(q@k^T)@v + q@prefix
// Epilogue writes fp16 Oh directly (single array; residual no longer needed).
// ---------------------------------------------------------------------------
#define KT_PITCH 68
#define ATTN_SMEM_FLOATS (4096 + CHUNK * KT_PITCH + 4096 + 4096)

__global__ __launch_bounds__(256) void attn_chunk_kernel() {
    extern __shared__ float smf[];
    float* qs = smf;
    float* kp = smf + 4096;
    float* vs = kp + CHUNK * KT_PITCH;
    float* ss = vs + 4096;

    const int tid = threadIdx.x;
    const int n = blockIdx.x & (NCHUNK - 1);
    const int bh = blockIdx.x >> 6;

    const float* qg = g_Q + ((size_t)bh * T_SEQ + n * CHUNK) * DHEAD;
    const float* kg = g_K + ((size_t)bh * T_SEQ + n * CHUNK) * DHEAD;
    const float* vg = g_V + ((size_t)bh * T_SEQ + n * CHUNK) * DHEAD;

    for (int f = tid; f < 1024; f += 256) {
        ((float4*)qs)[f] = ((const float4*)qg)[f];
        ((float4*)vs)[f] = ((const float4*)vg)[f];
        int j = f >> 4;
        int lq = (f & 15) << 2;
        float4 kv = ((const float4*)kg)[f];
        kp[(lq + 0) * KT_PITCH + j] = kv.x;
        kp[(lq + 1) * KT_PITCH + j] = kv.y;
        kp[(lq + 2) * KT_PITCH + j] = kv.z;
        kp[(lq + 3) * KT_PITCH + j] = kv.w;
    }
    __syncthreads();

    const int i0 = (tid >> 4) * 4;
    const int c0 = (tid & 15) * 4;

    {
        float sa[4][4] = {};
#pragma unroll 4
        for (int l = 0; l < DHEAD; l++) {
            float q4[4];
#pragma unroll
            for (int ii = 0; ii < 4; ii++) q4[ii] = qs[(i0 + ii) * DHEAD + l];
            float4 k4 = *(const float4*)&kp[l * KT_PITCH + c0];
#pragma unroll
            for (int ii = 0; ii < 4; ii++) {
                sa[ii][0] += q4[ii] * k4.x;
                sa[ii][1] += q4[ii] * k4.y;
                sa[ii][2] += q4[ii] * k4.z;
                sa[ii][3] += q4[ii] * k4.w;
            }
        }
#pragma unroll
        for (int ii = 0; ii < 4; ii++) {
            int i = i0 + ii;
#pragma unroll
            for (int jj = 0; jj < 4; jj++) {
                int j = c0 + jj;
                ss[i * CHUNK + j] = (j <= i) ? sa[ii][jj] : 0.f;
            }
        }
    }
    __syncthreads();

    {
        const float* pg = g_CKV + ((size_t)bh * NCHUNK + n) * (DHEAD * DHEAD);
        for (int f = tid; f < 1024; f += 256) ((float4*)kp)[f] = ((const float4*)pg)[f];
    }
    __syncthreads();

    {
        float oa[4][4] = {};
#pragma unroll 4
        for (int j = 0; j < CHUNK; j++) {
            float s4[4];
#pragma unroll
            for (int ii = 0; ii < 4; ii++) s4[ii] = ss[(i0 + ii) * CHUNK + j];
            float4 v4 = *(const float4*)&vs[j * DHEAD + c0];
#pragma unroll
            for (int ii = 0; ii < 4; ii++) {
                oa[ii][0] += s4[ii] * v4.x;
                oa[ii][1] += s4[ii] * v4.y;
                oa[ii][2] += s4[ii] * v4.z;
                oa[ii][3] += s4[ii] * v4.w;
            }
        }
#pragma unroll 4
        for (int k = 0; k < DHEAD; k++) {
            float q4[4];
#pragma unroll
            for (int ii = 0; ii < 4; ii++) q4[ii] = qs[(i0 + ii) * DHEAD + k];
            float4 p4 = *(const float4*)&kp[k * DHEAD + c0];
#pragma unroll
            for (int ii = 0; ii < 4; ii++) {
                oa[ii][0] += q4[ii] * p4.x;
                oa[ii][1] += q4[ii] * p4.y;
                oa[ii][2] += q4[ii] * p4.z;
                oa[ii][3] += q4[ii] * p4.w;
            }
        }
        // fused fp16 store (h only — residual product dropped from gemm1)
        __half* ohg = g_Oh + ((size_t)bh * T_SEQ + n * CHUNK) * DHEAD;
#pragma unroll
        for (int ii = 0; ii < 4; ii++) {
            __align__(8) __half hb[4];
#pragma unroll
            for (int jj = 0; jj < 4; jj++)
                hb[jj] = __float2half_rn(oa[ii][jj]);
            *(uint2*)(ohg + (i0 + ii) * DHEAD + c0) = *(uint2*)hb;
        }
    }
}

// ---------------------------------------------------------------------------
extern "C" void kernel_launch(void* const* d_in, const int* in_sizes, int n_in,
                              void* d_out, int out_size) {
    const float* x     = (const float*)d_in[0];
    const float* w_qkv = (const float*)d_in[1];
    const float* w_o   = (const float*)d_in[2];
    float* out = (float*)d_out;

    const int M = in_sizes[0] / DMODEL;    // 8192
    const int BH = (M / T_SEQ) * NHEADS;   // 32

    cudaFuncSetAttribute(gemm_mma<0>, cudaFuncAttributeMaxDynamicSharedMemorySize, GEMM_SMEM);
    cudaFuncSetAttribute(gemm_mma<1>, cudaFuncAttributeMaxDynamicSharedMemorySize, GEMM_SMEM);
    cudaFuncSetAttribute(attn_chunk_kernel, cudaFuncAttributeMaxDynamicSharedMemorySize,
                         ATTN_SMEM_FLOATS * (int)sizeof(float));

    reset_cnt_kernel<<<1, 32>>>();
    split_kernel<<<(M * DMODEL) / 1024, 256>>>(x, M * DMODEL, 0);
    split_kernel<<<(3 * DMODEL * DMODEL) / 1024, 256>>>(w_qkv, 3 * DMODEL * DMODEL, 1);
    split_kernel<<<(DMODEL * DMODEL) / 1024, 256>>>(w_o, DMODEL * DMODEL, 2);

    dim3 g1(3 * DMODEL / 128, M / 128);
    gemm_mma<0><<<g1, 256, GEMM_SMEM>>>(nullptr);

    fixup_kernel<<<256, 256>>>(x, w_qkv);

    chunk_kv_kernel<<<BH * NCHUNK, 256>>>();
    prefix_kernel<<<BH, 256>>>(out + (size_t)M * DMODEL);
    attn_chunk_kernel<<<BH * NCHUNK, 256, ATTN_SMEM_FLOATS * (int)sizeof(float)>>>();

    dim3 g2(DMODEL / 128, M / 128);
    gemm_mma<1><<<g2, 256, GEMM_SMEM>>>(out);
}